// round 14
// baseline (speedup 1.0000x reference)
#include <cuda_runtime.h>
#include <cuda_fp16.h>
#include <cstdint>

// ---------------------------------------------------------------------------
// GATEncoder: 3 layers of (GATConv + linear skip + ELU)
// N=50000, E=800000 (+N self loops), IN=128, H=4, C=64, HC=256
// Round 14: BK=64 2-stage GEMM (half the barriers, 2x MMA run length);
//           skip/acc buffer stored fp16 (halves its RW traffic).
// ---------------------------------------------------------------------------

#define NNODES 50000
#define NEDGES 800000
#define ETOT   (NEDGES + NNODES)
#define HC     256
#define SCAN_BLK 512
#define SSTR 72                         // halves per smem row (BK=64 + pad)
#define STG  (128 * SSTR)               // halves per matrix per stage
#define STAGE_B (3 * STG * 2)           // bytes per stage: A, Bh, Bl
#define GEMM_SMEM (2 * STAGE_B)         // 2 stages = 110592 B

// ------------------------- static device scratch ---------------------------
__device__ __half g_h16[(size_t)NNODES * HC];
__device__ __half g_acc[(size_t)NNODES * HC];   // skip + biases (fp16)
__device__ float g_s   [(size_t)NNODES * 4];
__device__ float g_d   [(size_t)NNODES * 4];
__device__ int   g_deg [NNODES];
__device__ int   g_cur [NNODES];
__device__ int   g_rp  [NNODES + 1];
__device__ int   g_csr [ETOT];
__device__ int   g_bsum[256];
__device__ __half g_a16[(size_t)NNODES * HC];
__device__ __half g_bh [3][131072];
__device__ __half g_bl [3][131072];

// ------------------------- helpers ----------------------------------------
__device__ __forceinline__ float lrelu(float v) { return v > 0.f ? v : 0.2f * v; }

__device__ __forceinline__ void mma16816(float* d, const uint32_t* a,
                                         uint32_t b0, uint32_t b1) {
    asm volatile(
        "mma.sync.aligned.m16n8k16.row.col.f32.f16.f16.f32 "
        "{%0,%1,%2,%3}, {%4,%5,%6,%7}, {%8,%9}, {%0,%1,%2,%3};"
        : "+f"(d[0]), "+f"(d[1]), "+f"(d[2]), "+f"(d[3])
        : "r"(a[0]), "r"(a[1]), "r"(a[2]), "r"(a[3]), "r"(b0), "r"(b1));
}

__device__ __forceinline__ void cp16(uint32_t dst, const __half* src, int srcsz) {
    asm volatile("cp.async.cg.shared.global [%0], [%1], 16, %2;"
                 :: "r"(dst), "l"(src), "r"(srcsz));
}

__device__ __forceinline__ void ldm_x4(uint32_t* r, uint32_t addr) {
    asm volatile("ldmatrix.sync.aligned.m8n8.x4.shared.b16 {%0,%1,%2,%3}, [%4];"
                 : "=r"(r[0]), "=r"(r[1]), "=r"(r[2]), "=r"(r[3]) : "r"(addr));
}
__device__ __forceinline__ void ldm_x2(uint32_t& r0, uint32_t& r1, uint32_t addr) {
    asm volatile("ldmatrix.sync.aligned.m8n8.x2.shared.b16 {%0,%1}, [%2];"
                 : "=r"(r0), "=r"(r1) : "r"(addr));
}

// ------------------------- prep ---------------------------------------------
__global__ void prep_kernel(const float* __restrict__ W1, const float* __restrict__ SW1,
                            const float* __restrict__ W2, const float* __restrict__ SW2,
                            const float* __restrict__ W3, const float* __restrict__ SW3,
                            __half* __restrict__ bh, __half* __restrict__ bl,
                            int* __restrict__ deg) {
    const int idx = blockIdx.x * blockDim.x + threadIdx.x;
    if (idx < NNODES) deg[idx] = 0;
    if (idx >= 327680) return;
    int l, which, mi, K;
    const float* src;
    if (idx < 65536)       { l = 0; K = 128; const int r = idx;          which = r >> 15; mi = r & 32767; src = which ? SW1 : W1; }
    else if (idx < 196608) { l = 1; K = 256; const int r = idx - 65536;  which = r >> 16; mi = r & 65535; src = which ? SW2 : W2; }
    else                   { l = 2; K = 256; const int r = idx - 196608; which = r >> 16; mi = r & 65535; src = which ? SW3 : W3; }
    const int k = mi >> 8;
    const int n = mi & 255;
    const float v = src[mi];
    const __half h = __float2half_rn(v);
    const size_t off = (size_t)l * 131072 + (size_t)(which * 256 + n) * K + k;
    bh[off] = h;
    bl[off] = __float2half_rn(v - __half2float(h));
}

// ------------------------- conv_a -------------------------------------------
__global__ void conv_a_kernel(const float* __restrict__ X,
                              __half* __restrict__ a16, int total) {
    const int idx = blockIdx.x * blockDim.x + threadIdx.x;
    if (idx >= total) return;
    a16[idx] = __float2half_rn(X[idx]);
}

// ------------------------- fused dual GEMM: BK=64, 2-stage, ldmatrix -------
__global__ __launch_bounds__(256, 2)
void gemm_mma_kernel(const __half* __restrict__ A,
                     const __half* __restrict__ Bh,
                     const __half* __restrict__ Bl,
                     __half* __restrict__ Ch16,
                     __half* __restrict__ Cacc16,
                     const float* __restrict__ bias1,
                     const float* __restrict__ bias2,
                     int M, int K) {
    extern __shared__ __half smem[];

    const int tid = threadIdx.x;
    const int wid = tid >> 5;
    const int lane = tid & 31;
    const int qr = lane >> 2;
    const int qc = (lane & 3) * 2;
    const int warp_m = (wid >> 2) * 64;
    const int warp_n = (wid & 3) * 32;
    const int m0 = blockIdx.y * 128;
    const int n0 = blockIdx.x * 128;

    float d[4][4][4];
#pragma unroll
    for (int mt = 0; mt < 4; mt++)
#pragma unroll
        for (int nt = 0; nt < 4; nt++)
#pragma unroll
            for (int r = 0; r < 4; r++) d[mt][nt][r] = 0.f;

    // loaders: 128 rows x 64 halves per matrix; thread -> row tid>>1,
    // k-half (tid&1)*32 halves, 4 x cp16 per matrix
    const int ar = tid >> 1;
    const int akh = (tid & 1) * 32;
    const int aguard = (m0 + ar < M) ? 16 : 0;
    const size_t abase = (size_t)(m0 + ar) * K + akh;
    const size_t bbase = (size_t)(n0 + ar) * K + akh;

    const uint32_t sbase = (uint32_t)__cvta_generic_to_shared(smem);
    const uint32_t stOfs = (uint32_t)(ar * SSTR + akh) * 2;

    uint32_t aofs[4], bofs[4];
#pragma unroll
    for (int mt = 0; mt < 4; mt++)
        aofs[mt] = (uint32_t)((warp_m + mt * 16 + (lane & 15)) * SSTR +
                              ((lane >> 4) << 3)) * 2;
#pragma unroll
    for (int nt = 0; nt < 4; nt++)
        bofs[nt] = (uint32_t)((warp_n + nt * 8 + (lane & 7)) * SSTR +
                              (((lane >> 3) & 1) << 3)) * 2;

    const int nch = K >> 6;   // BK=64

    // prologue: chunk 0 into stage 0
    {
        const uint32_t st = sbase;
#pragma unroll
        for (int j = 0; j < 4; j++) {
            cp16(st + stOfs + j * 16,               A + abase + j * 8,  aguard);
            cp16(st + STG * 2 + stOfs + j * 16,     Bh + bbase + j * 8, 16);
            cp16(st + 2 * STG * 2 + stOfs + j * 16, Bl + bbase + j * 8, 16);
        }
        asm volatile("cp.async.commit_group;");
    }

    for (int ch = 0; ch < nch; ch++) {
        asm volatile("cp.async.wait_group 0;");
        __syncthreads();   // data visible + prior compute done

        if (ch + 1 < nch) {
            const uint32_t st = sbase + ((ch + 1) & 1) * STAGE_B;
            const int kp = (ch + 1) << 6;
#pragma unroll
            for (int j = 0; j < 4; j++) {
                cp16(st + stOfs + j * 16,               A + abase + kp + j * 8,  aguard);
                cp16(st + STG * 2 + stOfs + j * 16,     Bh + bbase + kp + j * 8, 16);
                cp16(st + 2 * STG * 2 + stOfs + j * 16, Bl + bbase + kp + j * 8, 16);
            }
            asm volatile("cp.async.commit_group;");
        }

        const uint32_t stA  = sbase + (ch & 1) * STAGE_B;
        const uint32_t stBh = stA + STG * 2;
        const uint32_t stBl = stA + 2 * STG * 2;

#pragma unroll
        for (int ks = 0; ks < 4; ks++) {
            const uint32_t kb = ks * 32;   // 16 halves = 32 bytes
            uint32_t ah[4][4];
#pragma unroll
            for (int mt = 0; mt < 4; mt++)
                ldm_x4(ah[mt], stA + aofs[mt] + kb);
#pragma unroll
            for (int nt = 0; nt < 4; nt++) {
                uint32_t bh0, bh1, bl0, bl1;
                ldm_x2(bh0, bh1, stBh + bofs[nt] + kb);
                ldm_x2(bl0, bl1, stBl + bofs[nt] + kb);
#pragma unroll
                for (int mt = 0; mt < 4; mt++) {
                    mma16816(d[mt][nt], ah[mt], bh0, bh1);
                    mma16816(d[mt][nt], ah[mt], bl0, bl1);
                }
            }
        }
    }

#pragma unroll
    for (int nt = 0; nt < 4; nt++) {
        const int gcol = n0 + warp_n + nt * 8 + qc;
        if (gcol < 256) {
#pragma unroll
            for (int mt = 0; mt < 4; mt++) {
                const int r0 = m0 + warp_m + mt * 16 + qr;
                if (r0 < M) {
                    __half2 v = __floats2half2_rn(d[mt][nt][0], d[mt][nt][1]);
                    *(__half2*)&Ch16[(size_t)r0 * HC + gcol] = v;
                }
                if (r0 + 8 < M) {
                    __half2 v = __floats2half2_rn(d[mt][nt][2], d[mt][nt][3]);
                    *(__half2*)&Ch16[(size_t)(r0 + 8) * HC + gcol] = v;
                }
            }
        } else {
            const int col = gcol - 256;
            const float bv0 = bias1[col] + bias2[col];
            const float bv1 = bias1[col + 1] + bias2[col + 1];
#pragma unroll
            for (int mt = 0; mt < 4; mt++) {
                const int r0 = m0 + warp_m + mt * 16 + qr;
                if (r0 < M) {
                    __half2 v = __floats2half2_rn(d[mt][nt][0] + bv0, d[mt][nt][1] + bv1);
                    *(__half2*)&Cacc16[(size_t)r0 * HC + col] = v;
                }
                if (r0 + 8 < M) {
                    __half2 v = __floats2half2_rn(d[mt][nt][2] + bv0, d[mt][nt][3] + bv1);
                    *(__half2*)&Cacc16[(size_t)(r0 + 8) * HC + col] = v;
                }
            }
        }
    }
}

// ------------------------- CSR build ---------------------------------------
__global__ void hist_kernel(const int* __restrict__ ei, int* __restrict__ deg,
                            int nE, int nTot) {
    const int e = blockIdx.x * blockDim.x + threadIdx.x;
    if (e >= nTot) return;
    const int d = (e < nE) ? ei[nE + e] : (e - nE);
    atomicAdd(&deg[d], 1);
}

__global__ void scan1_kernel(const int* __restrict__ deg, int* __restrict__ bsum,
                             int n) {
    __shared__ int sh[256];
    const int b0 = blockIdx.x * SCAN_BLK;
    const int t = threadIdx.x;
    int s = 0;
    if (b0 + t < n)       s += deg[b0 + t];
    if (b0 + 256 + t < n) s += deg[b0 + 256 + t];
    sh[t] = s;
    __syncthreads();
    for (int off = 128; off > 0; off >>= 1) {
        if (t < off) sh[t] += sh[t + off];
        __syncthreads();
    }
    if (t == 0) bsum[blockIdx.x] = sh[0];
}

__global__ void scan2_kernel(int* __restrict__ bsum, int nb) {
    __shared__ int sh[256];
    const int t = threadIdx.x;
    sh[t] = (t < nb) ? bsum[t] : 0;
    __syncthreads();
    for (int off = 1; off < 256; off <<= 1) {
        const int v = (t >= off) ? sh[t - off] : 0;
        __syncthreads();
        sh[t] += v;
        __syncthreads();
    }
    if (t < nb) bsum[t] = (t == 0) ? 0 : sh[t - 1];
}

__global__ void scan3_kernel(const int* __restrict__ deg,
                             const int* __restrict__ bsum,
                             int* __restrict__ rp, int* __restrict__ cur,
                             int n) {
    __shared__ int sh[SCAN_BLK];
    const int b0 = blockIdx.x * SCAN_BLK;
    const int t = threadIdx.x;
    const int v0 = (b0 + t < n) ? deg[b0 + t] : 0;
    const int v1 = (b0 + 256 + t < n) ? deg[b0 + 256 + t] : 0;
    sh[t] = v0;
    sh[256 + t] = v1;
    __syncthreads();
    for (int off = 1; off < SCAN_BLK; off <<= 1) {
        const int a0 = (t >= off) ? sh[t - off] : 0;
        const int a1 = (t + 256 >= off) ? sh[t + 256 - off] : 0;
        __syncthreads();
        sh[t] += a0;
        sh[256 + t] += a1;
        __syncthreads();
    }
    const int base = bsum[blockIdx.x];
    if (b0 + t < n) {
        const int ex = base + sh[t] - v0;
        rp[b0 + t] = ex;
        cur[b0 + t] = ex;
    }
    if (b0 + 256 + t < n) {
        const int ex = base + sh[256 + t] - v1;
        rp[b0 + 256 + t] = ex;
        cur[b0 + 256 + t] = ex;
    }
    if (blockIdx.x == gridDim.x - 1 && t == 0) rp[n] = base + sh[SCAN_BLK - 1];
}

__global__ void scatter_kernel(const int* __restrict__ ei, int* __restrict__ cur,
                               int* __restrict__ csr, int nE, int nTot) {
    const int e = blockIdx.x * blockDim.x + threadIdx.x;
    if (e >= nTot) return;
    int s, d;
    if (e < nE) { s = ei[e]; d = ei[nE + e]; }
    else        { s = d = e - nE; }
    const int pos = atomicAdd(&cur[d], 1);
    csr[pos] = s;
}

// ------------------------- s/d per node (fp16 h) ----------------------------
__global__ void compute_sd_kernel(const __half* __restrict__ gh,
                                  const float* __restrict__ a_src,
                                  const float* __restrict__ a_dst,
                                  float* __restrict__ gs, float* __restrict__ gd,
                                  int n_nodes) {
    const int warp = (blockIdx.x * blockDim.x + threadIdx.x) >> 5;
    const int lane = threadIdx.x & 31;
    if (warp >= n_nodes) return;
    const __half* hr = gh + (size_t)warp * HC;
#pragma unroll
    for (int h = 0; h < 4; h++) {
        const float h1 = __half2float(hr[h * 64 + lane]);
        const float h2 = __half2float(hr[h * 64 + 32 + lane]);
        float s = h1 * a_src[h * 64 + lane] + h2 * a_src[h * 64 + 32 + lane];
        float d = h1 * a_dst[h * 64 + lane] + h2 * a_dst[h * 64 + 32 + lane];
#pragma unroll
        for (int off = 16; off > 0; off >>= 1) {
            s += __shfl_down_sync(0xFFFFFFFFu, s, off);
            d += __shfl_down_sync(0xFFFFFFFFu, d, off);
        }
        if (lane == 0) {
            gs[warp * 4 + h] = s;
            gd[warp * 4 + h] = d;
        }
    }
}

// ------------------------- fused softmax + aggregate + skip + ELU ----------
__global__ __launch_bounds__(256)
void node_agg_kernel(const int* __restrict__ rp, const int* __restrict__ csr,
                     const float* __restrict__ gs, const float* __restrict__ gd,
                     const __half* __restrict__ gh, const __half* __restrict__ gskip,
                     float* __restrict__ xout,
                     __half* __restrict__ x16,
                     int nN) {
    const int v = (blockIdx.x * blockDim.x + threadIdx.x) >> 5;
    const int lane = threadIdx.x & 31;
    if (v >= nN) return;

    const int b = rp[v];
    const int e = rp[v + 1];
    const float4 dv = ((const float4*)gd)[v];

    float m0 = -1e30f, m1 = -1e30f, m2 = -1e30f, m3 = -1e30f;
    for (int i = b + lane; i < e; i += 32) {
        const float4 sv = ((const float4*)gs)[csr[i]];
        m0 = fmaxf(m0, lrelu(sv.x + dv.x));
        m1 = fmaxf(m1, lrelu(sv.y + dv.y));
        m2 = fmaxf(m2, lrelu(sv.z + dv.z));
        m3 = fmaxf(m3, lrelu(sv.w + dv.w));
    }
#pragma unroll
    for (int off = 16; off > 0; off >>= 1) {
        m0 = fmaxf(m0, __shfl_xor_sync(0xFFFFFFFFu, m0, off));
        m1 = fmaxf(m1, __shfl_xor_sync(0xFFFFFFFFu, m1, off));
        m2 = fmaxf(m2, __shfl_xor_sync(0xFFFFFFFFu, m2, off));
        m3 = fmaxf(m3, __shfl_xor_sync(0xFFFFFFFFu, m3, off));
    }

    float n0 = 0.f, n1 = 0.f, n2 = 0.f, n3 = 0.f;
    for (int i = b + lane; i < e; i += 32) {
        const float4 sv = ((const float4*)gs)[csr[i]];
        n0 += expf(lrelu(sv.x + dv.x) - m0);
        n1 += expf(lrelu(sv.y + dv.y) - m1);
        n2 += expf(lrelu(sv.z + dv.z) - m2);
        n3 += expf(lrelu(sv.w + dv.w) - m3);
    }
#pragma unroll
    for (int off = 16; off > 0; off >>= 1) {
        n0 += __shfl_xor_sync(0xFFFFFFFFu, n0, off);
        n1 += __shfl_xor_sync(0xFFFFFFFFu, n1, off);
        n2 += __shfl_xor_sync(0xFFFFFFFFu, n2, off);
        n3 += __shfl_xor_sync(0xFFFFFFFFu, n3, off);
    }

    const int h = lane >> 3;
    const float dvh  = (h < 2) ? (h == 0 ? dv.x : dv.y) : (h == 2 ? dv.z : dv.w);
    const float mh   = (h < 2) ? (h == 0 ? m0 : m1) : (h == 2 ? m2 : m3);
    const float dnh  = (h < 2) ? (h == 0 ? n0 : n1) : (h == 2 ? n2 : n3);
    const float invh = 1.f / (dnh + 1e-16f);

    float4 a0 = make_float4(0.f, 0.f, 0.f, 0.f);
    float4 a1 = make_float4(0.f, 0.f, 0.f, 0.f);
#pragma unroll 2
    for (int i = b; i < e; i++) {
        const int s = csr[i];
        const float sval = gs[s * 4 + h];
        const float al = expf(lrelu(sval + dvh) - mh) * invh;
        const uint4 hv = *(const uint4*)(gh + (size_t)s * HC + lane * 8);
        const float2 f0 = __half22float2(*(const __half2*)&hv.x);
        const float2 f1 = __half22float2(*(const __half2*)&hv.y);
        const float2 f2 = __half22float2(*(const __half2*)&hv.z);
        const float2 f3 = __half22float2(*(const __half2*)&hv.w);
        a0.x = fmaf(f0.x, al, a0.x);  a0.y = fmaf(f0.y, al, a0.y);
        a0.z = fmaf(f1.x, al, a0.z);  a0.w = fmaf(f1.y, al, a0.w);
        a1.x = fmaf(f2.x, al, a1.x);  a1.y = fmaf(f2.y, al, a1.y);
        a1.z = fmaf(f3.x, al, a1.z);  a1.w = fmaf(f3.y, al, a1.w);
    }

    // skip (fp16) + ELU
    const uint4 sv4 = *(const uint4*)(gskip + (size_t)v * HC + lane * 8);
    const float2 s0 = __half22float2(*(const __half2*)&sv4.x);
    const float2 s1 = __half22float2(*(const __half2*)&sv4.y);
    const float2 s2 = __half22float2(*(const __half2*)&sv4.z);
    const float2 s3 = __half22float2(*(const __half2*)&sv4.w);
    float4 o0, o1;
    o0.x = a0.x + s0.x;  o0.y = a0.y + s0.y;  o0.z = a0.z + s1.x;  o0.w = a0.w + s1.y;
    o1.x = a1.x + s2.x;  o1.y = a1.y + s2.y;  o1.z = a1.z + s3.x;  o1.w = a1.w + s3.y;
    o0.x = o0.x > 0.f ? o0.x : expm1f(o0.x);
    o0.y = o0.y > 0.f ? o0.y : expm1f(o0.y);
    o0.z = o0.z > 0.f ? o0.z : expm1f(o0.z);
    o0.w = o0.w > 0.f ? o0.w : expm1f(o0.w);
    o1.x = o1.x > 0.f ? o1.x : expm1f(o1.x);
    o1.y = o1.y > 0.f ? o1.y : expm1f(o1.y);
    o1.z = o1.z > 0.f ? o1.z : expm1f(o1.z);
    o1.w = o1.w > 0.f ? o1.w : expm1f(o1.w);

    if (xout) {
        float4* op = (float4*)(xout + (size_t)v * HC) + lane * 2;
        op[0] = o0;
        op[1] = o1;
    }
    if (x16) {
        __half2 p0 = __floats2half2_rn(o0.x, o0.y);
        __half2 p1 = __floats2half2_rn(o0.z, o0.w);
        __half2 p2 = __floats2half2_rn(o1.x, o1.y);
        __half2 p3 = __floats2half2_rn(o1.z, o1.w);
        uint4 u = make_uint4(*(uint32_t*)&p0, *(uint32_t*)&p1,
                             *(uint32_t*)&p2, *(uint32_t*)&p3);
        *(uint4*)(x16 + (size_t)v * HC + lane * 8) = u;
    }
}

// ---------------------------------------------------------------------------
extern "C" void kernel_launch(void* const* d_in, const int* in_sizes, int n_in,
                              void* d_out, int out_size) {
    const float* x0 = (const float*)d_in[0];
    const int* ei = (const int*)d_in[1];
    const int nE = in_sizes[1] / 2;
    const int nN = NNODES;
    const int nTot = nE + nN;

    const float* W[3]    = {(const float*)d_in[2],  (const float*)d_in[8],  (const float*)d_in[14]};
    const float* ASRC[3] = {(const float*)d_in[3],  (const float*)d_in[9],  (const float*)d_in[15]};
    const float* ADST[3] = {(const float*)d_in[4],  (const float*)d_in[10], (const float*)d_in[16]};
    const float* BB[3]   = {(const float*)d_in[5],  (const float*)d_in[11], (const float*)d_in[17]};
    const float* SW[3]   = {(const float*)d_in[6],  (const float*)d_in[12], (const float*)d_in[18]};
    const float* SB[3]   = {(const float*)d_in[7],  (const float*)d_in[13], (const float*)d_in[19]};
    const int FIN[3] = {128, HC, HC};

    float *ps, *pd;
    int *pdeg, *pcur, *prp, *pcsr, *pbsum;
    __half *pbh, *pbl, *pa16, *ph16, *pacc;
    cudaGetSymbolAddress((void**)&ph16, g_h16);
    cudaGetSymbolAddress((void**)&pacc, g_acc);
    cudaGetSymbolAddress((void**)&ps,   g_s);
    cudaGetSymbolAddress((void**)&pd,   g_d);
    cudaGetSymbolAddress((void**)&pdeg, g_deg);
    cudaGetSymbolAddress((void**)&pcur, g_cur);
    cudaGetSymbolAddress((void**)&prp,  g_rp);
    cudaGetSymbolAddress((void**)&pcsr, g_csr);
    cudaGetSymbolAddress((void**)&pbsum,g_bsum);
    cudaGetSymbolAddress((void**)&pbh,  g_bh);
    cudaGetSymbolAddress((void**)&pbl,  g_bl);
    cudaGetSymbolAddress((void**)&pa16, g_a16);

    cudaFuncSetAttribute(gemm_mma_kernel,
                         cudaFuncAttributeMaxDynamicSharedMemorySize, GEMM_SMEM);

    const dim3 gemmGrid(4, (nN + 127) / 128);
    const int eBlocks   = (nTot + 255) / 256;
    const int sdBlocks  = (nN * 32 + 255) / 256;
    const int aggBlocks = (nN * 32 + 255) / 256;
    const int scanBlocks = (nN + SCAN_BLK - 1) / SCAN_BLK;

    prep_kernel<<<1280, 256>>>(W[0], SW[0], W[1], SW[1], W[2], SW[2],
                               pbh, pbl, pdeg);
    conv_a_kernel<<<(nN * 128 + 255) / 256, 256>>>(x0, pa16, nN * 128);
    hist_kernel<<<eBlocks, 256>>>(ei, pdeg, nE, nTot);

    // layer-1 GEMM (profiled by ncu)
    gemm_mma_kernel<<<gemmGrid, 256, GEMM_SMEM>>>(pa16, pbh, pbl, ph16, pacc,
                                                  BB[0], SB[0], nN, 128);

    scan1_kernel<<<scanBlocks, 256>>>(pdeg, pbsum, nN);
    scan2_kernel<<<1, 256>>>(pbsum, scanBlocks);
    scan3_kernel<<<scanBlocks, 256>>>(pdeg, pbsum, prp, pcur, nN);
    scatter_kernel<<<eBlocks, 256>>>(ei, pcur, pcsr, nE, nTot);

    for (int l = 0; l < 3; l++) {
        if (l > 0) {
            __half* bh = pbh + (size_t)l * 131072;
            __half* bl = pbl + (size_t)l * 131072;
            gemm_mma_kernel<<<gemmGrid, 256, GEMM_SMEM>>>(pa16, bh, bl, ph16, pacc,
                                                          BB[l], SB[l], nN, FIN[l]);
        }
        compute_sd_kernel<<<sdBlocks, 256>>>(ph16, ASRC[l], ADST[l], ps, pd, nN);
        float* xout = (l == 2) ? (float*)d_out : nullptr;
        __half* x16 = (l == 2) ? nullptr : pa16;
        node_agg_kernel<<<aggBlocks, 256>>>(prp, pcsr, ps, pd, ph16, pacc,
                                            xout, x16, nN);
    }
}

// round 15
// speedup vs baseline: 1.0573x; 1.0573x over previous
#include <cuda_runtime.h>
#include <cuda_fp16.h>
#include <cstdint>

// ---------------------------------------------------------------------------
// GATEncoder: 3 layers of (GATConv + linear skip + ELU)
// N=50000, E=800000 (+N self loops), IN=128, H=4, C=64, HC=256
// Round 15: GEMM mainloop reverted to round-13 (BK=32, 3-stage, ldmatrix —
//           BK=64 regressed); fp16 acc/skip kept (error model validated).
// ---------------------------------------------------------------------------

#define NNODES 50000
#define NEDGES 800000
#define ETOT   (NEDGES + NNODES)
#define HC     256
#define SCAN_BLK 512
#define SSTR 40
#define STG  (128 * SSTR)              // halves per matrix per stage
#define STAGE_B (3 * STG * 2)          // bytes per stage: A, Bh, Bl
#define GEMM_SMEM (3 * STAGE_B)        // 3 stages

// ------------------------- static device scratch ---------------------------
__device__ __half g_h16[(size_t)NNODES * HC];
__device__ __half g_acc[(size_t)NNODES * HC];   // skip + biases (fp16)
__device__ float g_s   [(size_t)NNODES * 4];
__device__ float g_d   [(size_t)NNODES * 4];
__device__ int   g_deg [NNODES];
__device__ int   g_cur [NNODES];
__device__ int   g_rp  [NNODES + 1];
__device__ int   g_csr [ETOT];
__device__ int   g_bsum[256];
__device__ __half g_a16[(size_t)NNODES * HC];
__device__ __half g_bh [3][131072];
__device__ __half g_bl [3][131072];

// ------------------------- helpers ----------------------------------------
__device__ __forceinline__ float lrelu(float v) { return v > 0.f ? v : 0.2f * v; }

__device__ __forceinline__ void mma16816(float* d, const uint32_t* a,
                                         uint32_t b0, uint32_t b1) {
    asm volatile(
        "mma.sync.aligned.m16n8k16.row.col.f32.f16.f16.f32 "
        "{%0,%1,%2,%3}, {%4,%5,%6,%7}, {%8,%9}, {%0,%1,%2,%3};"
        : "+f"(d[0]), "+f"(d[1]), "+f"(d[2]), "+f"(d[3])
        : "r"(a[0]), "r"(a[1]), "r"(a[2]), "r"(a[3]), "r"(b0), "r"(b1));
}

__device__ __forceinline__ void cp16(uint32_t dst, const __half* src, int srcsz) {
    asm volatile("cp.async.cg.shared.global [%0], [%1], 16, %2;"
                 :: "r"(dst), "l"(src), "r"(srcsz));
}

__device__ __forceinline__ void ldm_x4(uint32_t* r, uint32_t addr) {
    asm volatile("ldmatrix.sync.aligned.m8n8.x4.shared.b16 {%0,%1,%2,%3}, [%4];"
                 : "=r"(r[0]), "=r"(r[1]), "=r"(r[2]), "=r"(r[3]) : "r"(addr));
}
__device__ __forceinline__ void ldm_x2(uint32_t& r0, uint32_t& r1, uint32_t addr) {
    asm volatile("ldmatrix.sync.aligned.m8n8.x2.shared.b16 {%0,%1}, [%2];"
                 : "=r"(r0), "=r"(r1) : "r"(addr));
}

// ------------------------- prep ---------------------------------------------
__global__ void prep_kernel(const float* __restrict__ W1, const float* __restrict__ SW1,
                            const float* __restrict__ W2, const float* __restrict__ SW2,
                            const float* __restrict__ W3, const float* __restrict__ SW3,
                            __half* __restrict__ bh, __half* __restrict__ bl,
                            int* __restrict__ deg) {
    const int idx = blockIdx.x * blockDim.x + threadIdx.x;
    if (idx < NNODES) deg[idx] = 0;
    if (idx >= 327680) return;
    int l, which, mi, K;
    const float* src;
    if (idx < 65536)       { l = 0; K = 128; const int r = idx;          which = r >> 15; mi = r & 32767; src = which ? SW1 : W1; }
    else if (idx < 196608) { l = 1; K = 256; const int r = idx - 65536;  which = r >> 16; mi = r & 65535; src = which ? SW2 : W2; }
    else                   { l = 2; K = 256; const int r = idx - 196608; which = r >> 16; mi = r & 65535; src = which ? SW3 : W3; }
    const int k = mi >> 8;
    const int n = mi & 255;
    const float v = src[mi];
    const __half h = __float2half_rn(v);
    const size_t off = (size_t)l * 131072 + (size_t)(which * 256 + n) * K + k;
    bh[off] = h;
    bl[off] = __float2half_rn(v - __half2float(h));
}

// ------------------------- conv_a -------------------------------------------
__global__ void conv_a_kernel(const float* __restrict__ X,
                              __half* __restrict__ a16, int total) {
    const int idx = blockIdx.x * blockDim.x + threadIdx.x;
    if (idx >= total) return;
    a16[idx] = __float2half_rn(X[idx]);
}

// ------------------------- fused dual GEMM: BK=32, 3-stage, ldmatrix -------
__global__ __launch_bounds__(256, 2)
void gemm_mma_kernel(const __half* __restrict__ A,
                     const __half* __restrict__ Bh,
                     const __half* __restrict__ Bl,
                     __half* __restrict__ Ch16,
                     __half* __restrict__ Cacc16,
                     const float* __restrict__ bias1,
                     const float* __restrict__ bias2,
                     int M, int K) {
    extern __shared__ __half smem[];

    const int tid = threadIdx.x;
    const int wid = tid >> 5;
    const int lane = tid & 31;
    const int qr = lane >> 2;
    const int qc = (lane & 3) * 2;
    const int warp_m = (wid >> 2) * 64;
    const int warp_n = (wid & 3) * 32;
    const int m0 = blockIdx.y * 128;
    const int n0 = blockIdx.x * 128;

    float d[4][4][4];
#pragma unroll
    for (int mt = 0; mt < 4; mt++)
#pragma unroll
        for (int nt = 0; nt < 4; nt++)
#pragma unroll
            for (int r = 0; r < 4; r++) d[mt][nt][r] = 0.f;

    const int ar = tid >> 1;
    const int akh = (tid & 1) * 16;
    const int aguard = (m0 + ar < M) ? 16 : 0;
    const size_t abase = (size_t)(m0 + ar) * K + akh;
    const size_t bbase = (size_t)(n0 + ar) * K + akh;

    const uint32_t sbase = (uint32_t)__cvta_generic_to_shared(smem);
    const uint32_t stOfs = (uint32_t)(ar * SSTR + akh) * 2;

    uint32_t aofs[4], bofs[4];
#pragma unroll
    for (int mt = 0; mt < 4; mt++)
        aofs[mt] = (uint32_t)((warp_m + mt * 16 + (lane & 15)) * SSTR +
                              ((lane >> 4) << 3)) * 2;
#pragma unroll
    for (int nt = 0; nt < 4; nt++)
        bofs[nt] = (uint32_t)((warp_n + nt * 8 + (lane & 7)) * SSTR +
                              (((lane >> 3) & 1) << 3)) * 2;

    const int nch = K >> 5;

    // prologue: chunks 0,1 into stages 0,1
#pragma unroll
    for (int p = 0; p < 2; p++) {
        const uint32_t st = sbase + p * STAGE_B;
        const int kp = p << 5;
        cp16(st + stOfs,                  A + abase + kp,      aguard);
        cp16(st + stOfs + 16,             A + abase + kp + 8,  aguard);
        cp16(st + STG * 2 + stOfs,        Bh + bbase + kp,     16);
        cp16(st + STG * 2 + stOfs + 16,   Bh + bbase + kp + 8, 16);
        cp16(st + 2 * STG * 2 + stOfs,    Bl + bbase + kp,     16);
        cp16(st + 2 * STG * 2 + stOfs + 16, Bl + bbase + kp + 8, 16);
        asm volatile("cp.async.commit_group;");
    }

    int stage = 0;
    for (int ch = 0; ch < nch; ch++) {
        if (ch + 1 < nch) asm volatile("cp.async.wait_group 1;");
        else              asm volatile("cp.async.wait_group 0;");
        __syncthreads();

        if (ch + 2 < nch) {
            int s2 = stage + 2; if (s2 >= 3) s2 -= 3;
            const uint32_t st = sbase + s2 * STAGE_B;
            const int kp = (ch + 2) << 5;
            cp16(st + stOfs,                  A + abase + kp,      aguard);
            cp16(st + stOfs + 16,             A + abase + kp + 8,  aguard);
            cp16(st + STG * 2 + stOfs,        Bh + bbase + kp,     16);
            cp16(st + STG * 2 + stOfs + 16,   Bh + bbase + kp + 8, 16);
            cp16(st + 2 * STG * 2 + stOfs,    Bl + bbase + kp,     16);
            cp16(st + 2 * STG * 2 + stOfs + 16, Bl + bbase + kp + 8, 16);
            asm volatile("cp.async.commit_group;");
        }

        const uint32_t stA  = sbase + stage * STAGE_B;
        const uint32_t stBh = stA + STG * 2;
        const uint32_t stBl = stA + 2 * STG * 2;

#pragma unroll
        for (int ks = 0; ks < 2; ks++) {
            const uint32_t kb = ks * 32;
            uint32_t ah[4][4];
#pragma unroll
            for (int mt = 0; mt < 4; mt++)
                ldm_x4(ah[mt], stA + aofs[mt] + kb);
#pragma unroll
            for (int nt = 0; nt < 4; nt++) {
                uint32_t bh0, bh1, bl0, bl1;
                ldm_x2(bh0, bh1, stBh + bofs[nt] + kb);
                ldm_x2(bl0, bl1, stBl + bofs[nt] + kb);
#pragma unroll
                for (int mt = 0; mt < 4; mt++) {
                    mma16816(d[mt][nt], ah[mt], bh0, bh1);
                    mma16816(d[mt][nt], ah[mt], bl0, bl1);
                }
            }
        }
        if (++stage == 3) stage = 0;
    }

#pragma unroll
    for (int nt = 0; nt < 4; nt++) {
        const int gcol = n0 + warp_n + nt * 8 + qc;
        if (gcol < 256) {
#pragma unroll
            for (int mt = 0; mt < 4; mt++) {
                const int r0 = m0 + warp_m + mt * 16 + qr;
                if (r0 < M) {
                    __half2 v = __floats2half2_rn(d[mt][nt][0], d[mt][nt][1]);
                    *(__half2*)&Ch16[(size_t)r0 * HC + gcol] = v;
                }
                if (r0 + 8 < M) {
                    __half2 v = __floats2half2_rn(d[mt][nt][2], d[mt][nt][3]);
                    *(__half2*)&Ch16[(size_t)(r0 + 8) * HC + gcol] = v;
                }
            }
        } else {
            const int col = gcol - 256;
            const float bv0 = bias1[col] + bias2[col];
            const float bv1 = bias1[col + 1] + bias2[col + 1];
#pragma unroll
            for (int mt = 0; mt < 4; mt++) {
                const int r0 = m0 + warp_m + mt * 16 + qr;
                if (r0 < M) {
                    __half2 v = __floats2half2_rn(d[mt][nt][0] + bv0, d[mt][nt][1] + bv1);
                    *(__half2*)&Cacc16[(size_t)r0 * HC + col] = v;
                }
                if (r0 + 8 < M) {
                    __half2 v = __floats2half2_rn(d[mt][nt][2] + bv0, d[mt][nt][3] + bv1);
                    *(__half2*)&Cacc16[(size_t)(r0 + 8) * HC + col] = v;
                }
            }
        }
    }
}

// ------------------------- CSR build ---------------------------------------
__global__ void hist_kernel(const int* __restrict__ ei, int* __restrict__ deg,
                            int nE, int nTot) {
    const int e = blockIdx.x * blockDim.x + threadIdx.x;
    if (e >= nTot) return;
    const int d = (e < nE) ? ei[nE + e] : (e - nE);
    atomicAdd(&deg[d], 1);
}

__global__ void scan1_kernel(const int* __restrict__ deg, int* __restrict__ bsum,
                             int n) {
    __shared__ int sh[256];
    const int b0 = blockIdx.x * SCAN_BLK;
    const int t = threadIdx.x;
    int s = 0;
    if (b0 + t < n)       s += deg[b0 + t];
    if (b0 + 256 + t < n) s += deg[b0 + 256 + t];
    sh[t] = s;
    __syncthreads();
    for (int off = 128; off > 0; off >>= 1) {
        if (t < off) sh[t] += sh[t + off];
        __syncthreads();
    }
    if (t == 0) bsum[blockIdx.x] = sh[0];
}

__global__ void scan2_kernel(int* __restrict__ bsum, int nb) {
    __shared__ int sh[256];
    const int t = threadIdx.x;
    sh[t] = (t < nb) ? bsum[t] : 0;
    __syncthreads();
    for (int off = 1; off < 256; off <<= 1) {
        const int v = (t >= off) ? sh[t - off] : 0;
        __syncthreads();
        sh[t] += v;
        __syncthreads();
    }
    if (t < nb) bsum[t] = (t == 0) ? 0 : sh[t - 1];
}

__global__ void scan3_kernel(const int* __restrict__ deg,
                             const int* __restrict__ bsum,
                             int* __restrict__ rp, int* __restrict__ cur,
                             int n) {
    __shared__ int sh[SCAN_BLK];
    const int b0 = blockIdx.x * SCAN_BLK;
    const int t = threadIdx.x;
    const int v0 = (b0 + t < n) ? deg[b0 + t] : 0;
    const int v1 = (b0 + 256 + t < n) ? deg[b0 + 256 + t] : 0;
    sh[t] = v0;
    sh[256 + t] = v1;
    __syncthreads();
    for (int off = 1; off < SCAN_BLK; off <<= 1) {
        const int a0 = (t >= off) ? sh[t - off] : 0;
        const int a1 = (t + 256 >= off) ? sh[t + 256 - off] : 0;
        __syncthreads();
        sh[t] += a0;
        sh[256 + t] += a1;
        __syncthreads();
    }
    const int base = bsum[blockIdx.x];
    if (b0 + t < n) {
        const int ex = base + sh[t] - v0;
        rp[b0 + t] = ex;
        cur[b0 + t] = ex;
    }
    if (b0 + 256 + t < n) {
        const int ex = base + sh[256 + t] - v1;
        rp[b0 + 256 + t] = ex;
        cur[b0 + 256 + t] = ex;
    }
    if (blockIdx.x == gridDim.x - 1 && t == 0) rp[n] = base + sh[SCAN_BLK - 1];
}

__global__ void scatter_kernel(const int* __restrict__ ei, int* __restrict__ cur,
                               int* __restrict__ csr, int nE, int nTot) {
    const int e = blockIdx.x * blockDim.x + threadIdx.x;
    if (e >= nTot) return;
    int s, d;
    if (e < nE) { s = ei[e]; d = ei[nE + e]; }
    else        { s = d = e - nE; }
    const int pos = atomicAdd(&cur[d], 1);
    csr[pos] = s;
}

// ------------------------- s/d per node (fp16 h) ----------------------------
__global__ void compute_sd_kernel(const __half* __restrict__ gh,
                                  const float* __restrict__ a_src,
                                  const float* __restrict__ a_dst,
                                  float* __restrict__ gs, float* __restrict__ gd,
                                  int n_nodes) {
    const int warp = (blockIdx.x * blockDim.x + threadIdx.x) >> 5;
    const int lane = threadIdx.x & 31;
    if (warp >= n_nodes) return;
    const __half* hr = gh + (size_t)warp * HC;
#pragma unroll
    for (int h = 0; h < 4; h++) {
        const float h1 = __half2float(hr[h * 64 + lane]);
        const float h2 = __half2float(hr[h * 64 + 32 + lane]);
        float s = h1 * a_src[h * 64 + lane] + h2 * a_src[h * 64 + 32 + lane];
        float d = h1 * a_dst[h * 64 + lane] + h2 * a_dst[h * 64 + 32 + lane];
#pragma unroll
        for (int off = 16; off > 0; off >>= 1) {
            s += __shfl_down_sync(0xFFFFFFFFu, s, off);
            d += __shfl_down_sync(0xFFFFFFFFu, d, off);
        }
        if (lane == 0) {
            gs[warp * 4 + h] = s;
            gd[warp * 4 + h] = d;
        }
    }
}

// ------------------------- fused softmax + aggregate + skip + ELU ----------
__global__ __launch_bounds__(256)
void node_agg_kernel(const int* __restrict__ rp, const int* __restrict__ csr,
                     const float* __restrict__ gs, const float* __restrict__ gd,
                     const __half* __restrict__ gh, const __half* __restrict__ gskip,
                     float* __restrict__ xout,
                     __half* __restrict__ x16,
                     int nN) {
    const int v = (blockIdx.x * blockDim.x + threadIdx.x) >> 5;
    const int lane = threadIdx.x & 31;
    if (v >= nN) return;

    const int b = rp[v];
    const int e = rp[v + 1];
    const float4 dv = ((const float4*)gd)[v];

    float m0 = -1e30f, m1 = -1e30f, m2 = -1e30f, m3 = -1e30f;
    for (int i = b + lane; i < e; i += 32) {
        const float4 sv = ((const float4*)gs)[csr[i]];
        m0 = fmaxf(m0, lrelu(sv.x + dv.x));
        m1 = fmaxf(m1, lrelu(sv.y + dv.y));
        m2 = fmaxf(m2, lrelu(sv.z + dv.z));
        m3 = fmaxf(m3, lrelu(sv.w + dv.w));
    }
#pragma unroll
    for (int off = 16; off > 0; off >>= 1) {
        m0 = fmaxf(m0, __shfl_xor_sync(0xFFFFFFFFu, m0, off));
        m1 = fmaxf(m1, __shfl_xor_sync(0xFFFFFFFFu, m1, off));
        m2 = fmaxf(m2, __shfl_xor_sync(0xFFFFFFFFu, m2, off));
        m3 = fmaxf(m3, __shfl_xor_sync(0xFFFFFFFFu, m3, off));
    }

    float n0 = 0.f, n1 = 0.f, n2 = 0.f, n3 = 0.f;
    for (int i = b + lane; i < e; i += 32) {
        const float4 sv = ((const float4*)gs)[csr[i]];
        n0 += expf(lrelu(sv.x + dv.x) - m0);
        n1 += expf(lrelu(sv.y + dv.y) - m1);
        n2 += expf(lrelu(sv.z + dv.z) - m2);
        n3 += expf(lrelu(sv.w + dv.w) - m3);
    }
#pragma unroll
    for (int off = 16; off > 0; off >>= 1) {
        n0 += __shfl_xor_sync(0xFFFFFFFFu, n0, off);
        n1 += __shfl_xor_sync(0xFFFFFFFFu, n1, off);
        n2 += __shfl_xor_sync(0xFFFFFFFFu, n2, off);
        n3 += __shfl_xor_sync(0xFFFFFFFFu, n3, off);
    }

    const int h = lane >> 3;
    const float dvh  = (h < 2) ? (h == 0 ? dv.x : dv.y) : (h == 2 ? dv.z : dv.w);
    const float mh   = (h < 2) ? (h == 0 ? m0 : m1) : (h == 2 ? m2 : m3);
    const float dnh  = (h < 2) ? (h == 0 ? n0 : n1) : (h == 2 ? n2 : n3);
    const float invh = 1.f / (dnh + 1e-16f);

    float4 a0 = make_float4(0.f, 0.f, 0.f, 0.f);
    float4 a1 = make_float4(0.f, 0.f, 0.f, 0.f);
#pragma unroll 2
    for (int i = b; i < e; i++) {
        const int s = csr[i];
        const float sval = gs[s * 4 + h];
        const float al = expf(lrelu(sval + dvh) - mh) * invh;
        const uint4 hv = *(const uint4*)(gh + (size_t)s * HC + lane * 8);
        const float2 f0 = __half22float2(*(const __half2*)&hv.x);
        const float2 f1 = __half22float2(*(const __half2*)&hv.y);
        const float2 f2 = __half22float2(*(const __half2*)&hv.z);
        const float2 f3 = __half22float2(*(const __half2*)&hv.w);
        a0.x = fmaf(f0.x, al, a0.x);  a0.y = fmaf(f0.y, al, a0.y);
        a0.z = fmaf(f1.x, al, a0.z);  a0.w = fmaf(f1.y, al, a0.w);
        a1.x = fmaf(f2.x, al, a1.x);  a1.y = fmaf(f2.y, al, a1.y);
        a1.z = fmaf(f3.x, al, a1.z);  a1.w = fmaf(f3.y, al, a1.w);
    }

    // skip (fp16) + ELU
    const uint4 sv4 = *(const uint4*)(gskip + (size_t)v * HC + lane * 8);
    const float2 s0 = __half22float2(*(const __half2*)&sv4.x);
    const float2 s1 = __half22float2(*(const __half2*)&sv4.y);
    const float2 s2 = __half22float2(*(const __half2*)&sv4.z);
    const float2 s3 = __half22float2(*(const __half2*)&sv4.w);
    float4 o0, o1;
    o0.x = a0.x + s0.x;  o0.y = a0.y + s0.y;  o0.z = a0.z + s1.x;  o0.w = a0.w + s1.y;
    o1.x = a1.x + s2.x;  o1.y = a1.y + s2.y;  o1.z = a1.z + s3.x;  o1.w = a1.w + s3.y;
    o0.x = o0.x > 0.f ? o0.x : expm1f(o0.x);
    o0.y = o0.y > 0.f ? o0.y : expm1f(o0.y);
    o0.z = o0.z > 0.f ? o0.z : expm1f(o0.z);
    o0.w = o0.w > 0.f ? o0.w : expm1f(o0.w);
    o1.x = o1.x > 0.f ? o1.x : expm1f(o1.x);
    o1.y = o1.y > 0.f ? o1.y : expm1f(o1.y);
    o1.z = o1.z > 0.f ? o1.z : expm1f(o1.z);
    o1.w = o1.w > 0.f ? o1.w : expm1f(o1.w);

    if (xout) {
        float4* op = (float4*)(xout + (size_t)v * HC) + lane * 2;
        op[0] = o0;
        op[1] = o1;
    }
    if (x16) {
        __half2 p0 = __floats2half2_rn(o0.x, o0.y);
        __half2 p1 = __floats2half2_rn(o0.z, o0.w);
        __half2 p2 = __floats2half2_rn(o1.x, o1.y);
        __half2 p3 = __floats2half2_rn(o1.z, o1.w);
        uint4 u = make_uint4(*(uint32_t*)&p0, *(uint32_t*)&p1,
                             *(uint32_t*)&p2, *(uint32_t*)&p3);
        *(uint4*)(x16 + (size_t)v * HC + lane * 8) = u;
    }
}

// ---------------------------------------------------------------------------
extern "C" void kernel_launch(void* const* d_in, const int* in_sizes, int n_in,
                              void* d_out, int out_size) {
    const float* x0 = (const float*)d_in[0];
    const int* ei = (const int*)d_in[1];
    const int nE = in_sizes[1] / 2;
    const int nN = NNODES;
    const int nTot = nE + nN;

    const float* W[3]    = {(const float*)d_in[2],  (const float*)d_in[8],  (const float*)d_in[14]};
    const float* ASRC[3] = {(const float*)d_in[3],  (const float*)d_in[9],  (const float*)d_in[15]};
    const float* ADST[3] = {(const float*)d_in[4],  (const float*)d_in[10], (const float*)d_in[16]};
    const float* BB[3]   = {(const float*)d_in[5],  (const float*)d_in[11], (const float*)d_in[17]};
    const float* SW[3]   = {(const float*)d_in[6],  (const float*)d_in[12], (const float*)d_in[18]};
    const float* SB[3]   = {(const float*)d_in[7],  (const float*)d_in[13], (const float*)d_in[19]};
    const int FIN[3] = {128, HC, HC};

    float *ps, *pd;
    int *pdeg, *pcur, *prp, *pcsr, *pbsum;
    __half *pbh, *pbl, *pa16, *ph16, *pacc;
    cudaGetSymbolAddress((void**)&ph16, g_h16);
    cudaGetSymbolAddress((void**)&pacc, g_acc);
    cudaGetSymbolAddress((void**)&ps,   g_s);
    cudaGetSymbolAddress((void**)&pd,   g_d);
    cudaGetSymbolAddress((void**)&pdeg, g_deg);
    cudaGetSymbolAddress((void**)&pcur, g_cur);
    cudaGetSymbolAddress((void**)&prp,  g_rp);
    cudaGetSymbolAddress((void**)&pcsr, g_csr);
    cudaGetSymbolAddress((void**)&pbsum,g_bsum);
    cudaGetSymbolAddress((void**)&pbh,  g_bh);
    cudaGetSymbolAddress((void**)&pbl,  g_bl);
    cudaGetSymbolAddress((void**)&pa16, g_a16);

    cudaFuncSetAttribute(gemm_mma_kernel,
                         cudaFuncAttributeMaxDynamicSharedMemorySize, GEMM_SMEM);

    const dim3 gemmGrid(4, (nN + 127) / 128);
    const int eBlocks   = (nTot + 255) / 256;
    const int sdBlocks  = (nN * 32 + 255) / 256;
    const int aggBlocks = (nN * 32 + 255) / 256;
    const int scanBlocks = (nN + SCAN_BLK - 1) / SCAN_BLK;

    prep_kernel<<<1280, 256>>>(W[0], SW[0], W[1], SW[1], W[2], SW[2],
                               pbh, pbl, pdeg);
    conv_a_kernel<<<(nN * 128 + 255) / 256, 256>>>(x0, pa16, nN * 128);
    hist_kernel<<<eBlocks, 256>>>(ei, pdeg, nE, nTot);

    // layer-1 GEMM (profiled by ncu)
    gemm_mma_kernel<<<gemmGrid, 256, GEMM_SMEM>>>(pa16, pbh, pbl, ph16, pacc,
                                                  BB[0], SB[0], nN, 128);

    scan1_kernel<<<scanBlocks, 256>>>(pdeg, pbsum, nN);
    scan2_kernel<<<1, 256>>>(pbsum, scanBlocks);
    scan3_kernel<<<scanBlocks, 256>>>(pdeg, pbsum, prp, pcur, nN);
    scatter_kernel<<<eBlocks, 256>>>(ei, pcur, pcsr, nE, nTot);

    for (int l = 0; l < 3; l++) {
        if (l > 0) {
            __half* bh = pbh + (size_t)l * 131072;
            __half* bl = pbl + (size_t)l * 131072;
            gemm_mma_kernel<<<gemmGrid, 256, GEMM_SMEM>>>(pa16, bh, bl, ph16, pacc,
                                                          BB[l], SB[l], nN, FIN[l]);
        }
        compute_sd_kernel<<<sdBlocks, 256>>>(ph16, ASRC[l], ADST[l], ps, pd, nN);
        float* xout = (l == 2) ? (float*)d_out : nullptr;
        __half* x16 = (l == 2) ? nullptr : pa16;
        node_agg_kernel<<<aggBlocks, 256>>>(prp, pcsr, ps, pd, ph16, pacc,
                                            xout, x16, nN);
    }
}

// round 16
// speedup vs baseline: 1.2229x; 1.1566x over previous
#include <cuda_runtime.h>
#include <cuda_fp16.h>
#include <cstdint>

// ---------------------------------------------------------------------------
// GATEncoder: 3 layers of (GATConv + linear skip + ELU)
// N=50000, E=800000 (+N self loops), IN=128, H=4, C=64, HC=256
// Round 16: plain fp16 GEMM (B-lo correction dropped; calibrated error model
//           predicts ~6.3e-4 < 1e-3). BK=32, 3-stage, ldmatrix pipeline kept.
// ---------------------------------------------------------------------------

#define NNODES 50000
#define NEDGES 800000
#define ETOT   (NEDGES + NNODES)
#define HC     256
#define SCAN_BLK 512
#define SSTR 40
#define STG  (128 * SSTR)              // halves per matrix per stage
#define STAGE_B (2 * STG * 2)          // bytes per stage: A, B
#define GEMM_SMEM (3 * STAGE_B)        // 3 stages

// ------------------------- static device scratch ---------------------------
__device__ __half g_h16[(size_t)NNODES * HC];
__device__ __half g_acc[(size_t)NNODES * HC];   // skip + biases (fp16)
__device__ float g_s   [(size_t)NNODES * 4];
__device__ float g_d   [(size_t)NNODES * 4];
__device__ int   g_deg [NNODES];
__device__ int   g_cur [NNODES];
__device__ int   g_rp  [NNODES + 1];
__device__ int   g_csr [ETOT];
__device__ int   g_bsum[256];
__device__ __half g_a16[(size_t)NNODES * HC];
__device__ __half g_bh [3][131072];             // fused [512,K] fp16 weights

// ------------------------- helpers ----------------------------------------
__device__ __forceinline__ float lrelu(float v) { return v > 0.f ? v : 0.2f * v; }

__device__ __forceinline__ void mma16816(float* d, const uint32_t* a,
                                         uint32_t b0, uint32_t b1) {
    asm volatile(
        "mma.sync.aligned.m16n8k16.row.col.f32.f16.f16.f32 "
        "{%0,%1,%2,%3}, {%4,%5,%6,%7}, {%8,%9}, {%0,%1,%2,%3};"
        : "+f"(d[0]), "+f"(d[1]), "+f"(d[2]), "+f"(d[3])
        : "r"(a[0]), "r"(a[1]), "r"(a[2]), "r"(a[3]), "r"(b0), "r"(b1));
}

__device__ __forceinline__ void cp16(uint32_t dst, const __half* src, int srcsz) {
    asm volatile("cp.async.cg.shared.global [%0], [%1], 16, %2;"
                 :: "r"(dst), "l"(src), "r"(srcsz));
}

__device__ __forceinline__ void ldm_x4(uint32_t* r, uint32_t addr) {
    asm volatile("ldmatrix.sync.aligned.m8n8.x4.shared.b16 {%0,%1,%2,%3}, [%4];"
                 : "=r"(r[0]), "=r"(r[1]), "=r"(r[2]), "=r"(r[3]) : "r"(addr));
}
__device__ __forceinline__ void ldm_x2(uint32_t& r0, uint32_t& r1, uint32_t addr) {
    asm volatile("ldmatrix.sync.aligned.m8n8.x2.shared.b16 {%0,%1}, [%2];"
                 : "=r"(r0), "=r"(r1) : "r"(addr));
}

// ------------------------- prep ---------------------------------------------
__global__ void prep_kernel(const float* __restrict__ W1, const float* __restrict__ SW1,
                            const float* __restrict__ W2, const float* __restrict__ SW2,
                            const float* __restrict__ W3, const float* __restrict__ SW3,
                            __half* __restrict__ bh,
                            int* __restrict__ deg) {
    const int idx = blockIdx.x * blockDim.x + threadIdx.x;
    if (idx < NNODES) deg[idx] = 0;
    if (idx >= 327680) return;
    int l, which, mi, K;
    const float* src;
    if (idx < 65536)       { l = 0; K = 128; const int r = idx;          which = r >> 15; mi = r & 32767; src = which ? SW1 : W1; }
    else if (idx < 196608) { l = 1; K = 256; const int r = idx - 65536;  which = r >> 16; mi = r & 65535; src = which ? SW2 : W2; }
    else                   { l = 2; K = 256; const int r = idx - 196608; which = r >> 16; mi = r & 65535; src = which ? SW3 : W3; }
    const int k = mi >> 8;
    const int n = mi & 255;
    const size_t off = (size_t)l * 131072 + (size_t)(which * 256 + n) * K + k;
    bh[off] = __float2half_rn(src[mi]);
}

// ------------------------- conv_a -------------------------------------------
__global__ void conv_a_kernel(const float* __restrict__ X,
                              __half* __restrict__ a16, int total) {
    const int idx = blockIdx.x * blockDim.x + threadIdx.x;
    if (idx >= total) return;
    a16[idx] = __float2half_rn(X[idx]);
}

// ------------------------- fused dual GEMM: plain fp16, 3-stage, ldmatrix --
__global__ __launch_bounds__(256, 2)
void gemm_mma_kernel(const __half* __restrict__ A,
                     const __half* __restrict__ Bh,
                     __half* __restrict__ Ch16,
                     __half* __restrict__ Cacc16,
                     const float* __restrict__ bias1,
                     const float* __restrict__ bias2,
                     int M, int K) {
    extern __shared__ __half smem[];

    const int tid = threadIdx.x;
    const int wid = tid >> 5;
    const int lane = tid & 31;
    const int qr = lane >> 2;
    const int qc = (lane & 3) * 2;
    const int warp_m = (wid >> 2) * 64;
    const int warp_n = (wid & 3) * 32;
    const int m0 = blockIdx.y * 128;
    const int n0 = blockIdx.x * 128;

    float d[4][4][4];
#pragma unroll
    for (int mt = 0; mt < 4; mt++)
#pragma unroll
        for (int nt = 0; nt < 4; nt++)
#pragma unroll
            for (int r = 0; r < 4; r++) d[mt][nt][r] = 0.f;

    const int ar = tid >> 1;
    const int akh = (tid & 1) * 16;
    const int aguard = (m0 + ar < M) ? 16 : 0;
    const size_t abase = (size_t)(m0 + ar) * K + akh;
    const size_t bbase = (size_t)(n0 + ar) * K + akh;

    const uint32_t sbase = (uint32_t)__cvta_generic_to_shared(smem);
    const uint32_t stOfs = (uint32_t)(ar * SSTR + akh) * 2;

    uint32_t aofs[4], bofs[4];
#pragma unroll
    for (int mt = 0; mt < 4; mt++)
        aofs[mt] = (uint32_t)((warp_m + mt * 16 + (lane & 15)) * SSTR +
                              ((lane >> 4) << 3)) * 2;
#pragma unroll
    for (int nt = 0; nt < 4; nt++)
        bofs[nt] = (uint32_t)((warp_n + nt * 8 + (lane & 7)) * SSTR +
                              (((lane >> 3) & 1) << 3)) * 2;

    const int nch = K >> 5;

    // prologue: chunks 0,1 into stages 0,1
#pragma unroll
    for (int p = 0; p < 2; p++) {
        const uint32_t st = sbase + p * STAGE_B;
        const int kp = p << 5;
        cp16(st + stOfs,                A + abase + kp,      aguard);
        cp16(st + stOfs + 16,           A + abase + kp + 8,  aguard);
        cp16(st + STG * 2 + stOfs,      Bh + bbase + kp,     16);
        cp16(st + STG * 2 + stOfs + 16, Bh + bbase + kp + 8, 16);
        asm volatile("cp.async.commit_group;");
    }

    int stage = 0;
    for (int ch = 0; ch < nch; ch++) {
        if (ch + 1 < nch) asm volatile("cp.async.wait_group 1;");
        else              asm volatile("cp.async.wait_group 0;");
        __syncthreads();

        if (ch + 2 < nch) {
            int s2 = stage + 2; if (s2 >= 3) s2 -= 3;
            const uint32_t st = sbase + s2 * STAGE_B;
            const int kp = (ch + 2) << 5;
            cp16(st + stOfs,                A + abase + kp,      aguard);
            cp16(st + stOfs + 16,           A + abase + kp + 8,  aguard);
            cp16(st + STG * 2 + stOfs,      Bh + bbase + kp,     16);
            cp16(st + STG * 2 + stOfs + 16, Bh + bbase + kp + 8, 16);
            asm volatile("cp.async.commit_group;");
        }

        const uint32_t stA  = sbase + stage * STAGE_B;
        const uint32_t stBh = stA + STG * 2;

#pragma unroll
        for (int ks = 0; ks < 2; ks++) {
            const uint32_t kb = ks * 32;
            uint32_t ah[4][4];
#pragma unroll
            for (int mt = 0; mt < 4; mt++)
                ldm_x4(ah[mt], stA + aofs[mt] + kb);
#pragma unroll
            for (int nt = 0; nt < 4; nt++) {
                uint32_t bh0, bh1;
                ldm_x2(bh0, bh1, stBh + bofs[nt] + kb);
#pragma unroll
                for (int mt = 0; mt < 4; mt++)
                    mma16816(d[mt][nt], ah[mt], bh0, bh1);
            }
        }
        if (++stage == 3) stage = 0;
    }

#pragma unroll
    for (int nt = 0; nt < 4; nt++) {
        const int gcol = n0 + warp_n + nt * 8 + qc;
        if (gcol < 256) {
#pragma unroll
            for (int mt = 0; mt < 4; mt++) {
                const int r0 = m0 + warp_m + mt * 16 + qr;
                if (r0 < M) {
                    __half2 v = __floats2half2_rn(d[mt][nt][0], d[mt][nt][1]);
                    *(__half2*)&Ch16[(size_t)r0 * HC + gcol] = v;
                }
                if (r0 + 8 < M) {
                    __half2 v = __floats2half2_rn(d[mt][nt][2], d[mt][nt][3]);
                    *(__half2*)&Ch16[(size_t)(r0 + 8) * HC + gcol] = v;
                }
            }
        } else {
            const int col = gcol - 256;
            const float bv0 = bias1[col] + bias2[col];
            const float bv1 = bias1[col + 1] + bias2[col + 1];
#pragma unroll
            for (int mt = 0; mt < 4; mt++) {
                const int r0 = m0 + warp_m + mt * 16 + qr;
                if (r0 < M) {
                    __half2 v = __floats2half2_rn(d[mt][nt][0] + bv0, d[mt][nt][1] + bv1);
                    *(__half2*)&Cacc16[(size_t)r0 * HC + col] = v;
                }
                if (r0 + 8 < M) {
                    __half2 v = __floats2half2_rn(d[mt][nt][2] + bv0, d[mt][nt][3] + bv1);
                    *(__half2*)&Cacc16[(size_t)(r0 + 8) * HC + col] = v;
                }
            }
        }
    }
}

// ------------------------- CSR build ---------------------------------------
__global__ void hist_kernel(const int* __restrict__ ei, int* __restrict__ deg,
                            int nE, int nTot) {
    const int e = blockIdx.x * blockDim.x + threadIdx.x;
    if (e >= nTot) return;
    const int d = (e < nE) ? ei[nE + e] : (e - nE);
    atomicAdd(&deg[d], 1);
}

__global__ void scan1_kernel(const int* __restrict__ deg, int* __restrict__ bsum,
                             int n) {
    __shared__ int sh[256];
    const int b0 = blockIdx.x * SCAN_BLK;
    const int t = threadIdx.x;
    int s = 0;
    if (b0 + t < n)       s += deg[b0 + t];
    if (b0 + 256 + t < n) s += deg[b0 + 256 + t];
    sh[t] = s;
    __syncthreads();
    for (int off = 128; off > 0; off >>= 1) {
        if (t < off) sh[t] += sh[t + off];
        __syncthreads();
    }
    if (t == 0) bsum[blockIdx.x] = sh[0];
}

__global__ void scan2_kernel(int* __restrict__ bsum, int nb) {
    __shared__ int sh[256];
    const int t = threadIdx.x;
    sh[t] = (t < nb) ? bsum[t] : 0;
    __syncthreads();
    for (int off = 1; off < 256; off <<= 1) {
        const int v = (t >= off) ? sh[t - off] : 0;
        __syncthreads();
        sh[t] += v;
        __syncthreads();
    }
    if (t < nb) bsum[t] = (t == 0) ? 0 : sh[t - 1];
}

__global__ void scan3_kernel(const int* __restrict__ deg,
                             const int* __restrict__ bsum,
                             int* __restrict__ rp, int* __restrict__ cur,
                             int n) {
    __shared__ int sh[SCAN_BLK];
    const int b0 = blockIdx.x * SCAN_BLK;
    const int t = threadIdx.x;
    const int v0 = (b0 + t < n) ? deg[b0 + t] : 0;
    const int v1 = (b0 + 256 + t < n) ? deg[b0 + 256 + t] : 0;
    sh[t] = v0;
    sh[256 + t] = v1;
    __syncthreads();
    for (int off = 1; off < SCAN_BLK; off <<= 1) {
        const int a0 = (t >= off) ? sh[t - off] : 0;
        const int a1 = (t + 256 >= off) ? sh[t + 256 - off] : 0;
        __syncthreads();
        sh[t] += a0;
        sh[256 + t] += a1;
        __syncthreads();
    }
    const int base = bsum[blockIdx.x];
    if (b0 + t < n) {
        const int ex = base + sh[t] - v0;
        rp[b0 + t] = ex;
        cur[b0 + t] = ex;
    }
    if (b0 + 256 + t < n) {
        const int ex = base + sh[256 + t] - v1;
        rp[b0 + 256 + t] = ex;
        cur[b0 + 256 + t] = ex;
    }
    if (blockIdx.x == gridDim.x - 1 && t == 0) rp[n] = base + sh[SCAN_BLK - 1];
}

__global__ void scatter_kernel(const int* __restrict__ ei, int* __restrict__ cur,
                               int* __restrict__ csr, int nE, int nTot) {
    const int e = blockIdx.x * blockDim.x + threadIdx.x;
    if (e >= nTot) return;
    int s, d;
    if (e < nE) { s = ei[e]; d = ei[nE + e]; }
    else        { s = d = e - nE; }
    const int pos = atomicAdd(&cur[d], 1);
    csr[pos] = s;
}

// ------------------------- s/d per node (fp16 h) ----------------------------
__global__ void compute_sd_kernel(const __half* __restrict__ gh,
                                  const float* __restrict__ a_src,
                                  const float* __restrict__ a_dst,
                                  float* __restrict__ gs, float* __restrict__ gd,
                                  int n_nodes) {
    const int warp = (blockIdx.x * blockDim.x + threadIdx.x) >> 5;
    const int lane = threadIdx.x & 31;
    if (warp >= n_nodes) return;
    const __half* hr = gh + (size_t)warp * HC;
#pragma unroll
    for (int h = 0; h < 4; h++) {
        const float h1 = __half2float(hr[h * 64 + lane]);
        const float h2 = __half2float(hr[h * 64 + 32 + lane]);
        float s = h1 * a_src[h * 64 + lane] + h2 * a_src[h * 64 + 32 + lane];
        float d = h1 * a_dst[h * 64 + lane] + h2 * a_dst[h * 64 + 32 + lane];
#pragma unroll
        for (int off = 16; off > 0; off >>= 1) {
            s += __shfl_down_sync(0xFFFFFFFFu, s, off);
            d += __shfl_down_sync(0xFFFFFFFFu, d, off);
        }
        if (lane == 0) {
            gs[warp * 4 + h] = s;
            gd[warp * 4 + h] = d;
        }
    }
}

// ------------------------- fused softmax + aggregate + skip + ELU ----------
__global__ __launch_bounds__(256)
void node_agg_kernel(const int* __restrict__ rp, const int* __restrict__ csr,
                     const float* __restrict__ gs, const float* __restrict__ gd,
                     const __half* __restrict__ gh, const __half* __restrict__ gskip,
                     float* __restrict__ xout,
                     __half* __restrict__ x16,
                     int nN) {
    const int v = (blockIdx.x * blockDim.x + threadIdx.x) >> 5;
    const int lane = threadIdx.x & 31;
    if (v >= nN) return;

    const int b = rp[v];
    const int e = rp[v + 1];
    const float4 dv = ((const float4*)gd)[v];

    float m0 = -1e30f, m1 = -1e30f, m2 = -1e30f, m3 = -1e30f;
    for (int i = b + lane; i < e; i += 32) {
        const float4 sv = ((const float4*)gs)[csr[i]];
        m0 = fmaxf(m0, lrelu(sv.x + dv.x));
        m1 = fmaxf(m1, lrelu(sv.y + dv.y));
        m2 = fmaxf(m2, lrelu(sv.z + dv.z));
        m3 = fmaxf(m3, lrelu(sv.w + dv.w));
    }
#pragma unroll
    for (int off = 16; off > 0; off >>= 1) {
        m0 = fmaxf(m0, __shfl_xor_sync(0xFFFFFFFFu, m0, off));
        m1 = fmaxf(m1, __shfl_xor_sync(0xFFFFFFFFu, m1, off));
        m2 = fmaxf(m2, __shfl_xor_sync(0xFFFFFFFFu, m2, off));
        m3 = fmaxf(m3, __shfl_xor_sync(0xFFFFFFFFu, m3, off));
    }

    float n0 = 0.f, n1 = 0.f, n2 = 0.f, n3 = 0.f;
    for (int i = b + lane; i < e; i += 32) {
        const float4 sv = ((const float4*)gs)[csr[i]];
        n0 += expf(lrelu(sv.x + dv.x) - m0);
        n1 += expf(lrelu(sv.y + dv.y) - m1);
        n2 += expf(lrelu(sv.z + dv.z) - m2);
        n3 += expf(lrelu(sv.w + dv.w) - m3);
    }
#pragma unroll
    for (int off = 16; off > 0; off >>= 1) {
        n0 += __shfl_xor_sync(0xFFFFFFFFu, n0, off);
        n1 += __shfl_xor_sync(0xFFFFFFFFu, n1, off);
        n2 += __shfl_xor_sync(0xFFFFFFFFu, n2, off);
        n3 += __shfl_xor_sync(0xFFFFFFFFu, n3, off);
    }

    const int h = lane >> 3;
    const float dvh  = (h < 2) ? (h == 0 ? dv.x : dv.y) : (h == 2 ? dv.z : dv.w);
    const float mh   = (h < 2) ? (h == 0 ? m0 : m1) : (h == 2 ? m2 : m3);
    const float dnh  = (h < 2) ? (h == 0 ? n0 : n1) : (h == 2 ? n2 : n3);
    const float invh = 1.f / (dnh + 1e-16f);

    float4 a0 = make_float4(0.f, 0.f, 0.f, 0.f);
    float4 a1 = make_float4(0.f, 0.f, 0.f, 0.f);
#pragma unroll 2
    for (int i = b; i < e; i++) {
        const int s = csr[i];
        const float sval = gs[s * 4 + h];
        const float al = expf(lrelu(sval + dvh) - mh) * invh;
        const uint4 hv = *(const uint4*)(gh + (size_t)s * HC + lane * 8);
        const float2 f0 = __half22float2(*(const __half2*)&hv.x);
        const float2 f1 = __half22float2(*(const __half2*)&hv.y);
        const float2 f2 = __half22float2(*(const __half2*)&hv.z);
        const float2 f3 = __half22float2(*(const __half2*)&hv.w);
        a0.x = fmaf(f0.x, al, a0.x);  a0.y = fmaf(f0.y, al, a0.y);
        a0.z = fmaf(f1.x, al, a0.z);  a0.w = fmaf(f1.y, al, a0.w);
        a1.x = fmaf(f2.x, al, a1.x);  a1.y = fmaf(f2.y, al, a1.y);
        a1.z = fmaf(f3.x, al, a1.z);  a1.w = fmaf(f3.y, al, a1.w);
    }

    const uint4 sv4 = *(const uint4*)(gskip + (size_t)v * HC + lane * 8);
    const float2 s0 = __half22float2(*(const __half2*)&sv4.x);
    const float2 s1 = __half22float2(*(const __half2*)&sv4.y);
    const float2 s2 = __half22float2(*(const __half2*)&sv4.z);
    const float2 s3 = __half22float2(*(const __half2*)&sv4.w);
    float4 o0, o1;
    o0.x = a0.x + s0.x;  o0.y = a0.y + s0.y;  o0.z = a0.z + s1.x;  o0.w = a0.w + s1.y;
    o1.x = a1.x + s2.x;  o1.y = a1.y + s2.y;  o1.z = a1.z + s3.x;  o1.w = a1.w + s3.y;
    o0.x = o0.x > 0.f ? o0.x : expm1f(o0.x);
    o0.y = o0.y > 0.f ? o0.y : expm1f(o0.y);
    o0.z = o0.z > 0.f ? o0.z : expm1f(o0.z);
    o0.w = o0.w > 0.f ? o0.w : expm1f(o0.w);
    o1.x = o1.x > 0.f ? o1.x : expm1f(o1.x);
    o1.y = o1.y > 0.f ? o1.y : expm1f(o1.y);
    o1.z = o1.z > 0.f ? o1.z : expm1f(o1.z);
    o1.w = o1.w > 0.f ? o1.w : expm1f(o1.w);

    if (xout) {
        float4* op = (float4*)(xout + (size_t)v * HC) + lane * 2;
        op[0] = o0;
        op[1] = o1;
    }
    if (x16) {
        __half2 p0 = __floats2half2_rn(o0.x, o0.y);
        __half2 p1 = __floats2half2_rn(o0.z, o0.w);
        __half2 p2 = __floats2half2_rn(o1.x, o1.y);
        __half2 p3 = __floats2half2_rn(o1.z, o1.w);
        uint4 u = make_uint4(*(uint32_t*)&p0, *(uint32_t*)&p1,
                             *(uint32_t*)&p2, *(uint32_t*)&p3);
        *(uint4*)(x16 + (size_t)v * HC + lane * 8) = u;
    }
}

// ---------------------------------------------------------------------------
extern "C" void kernel_launch(void* const* d_in, const int* in_sizes, int n_in,
                              void* d_out, int out_size) {
    const float* x0 = (const float*)d_in[0];
    const int* ei = (const int*)d_in[1];
    const int nE = in_sizes[1] / 2;
    const int nN = NNODES;
    const int nTot = nE + nN;

    const float* W[3]    = {(const float*)d_in[2],  (const float*)d_in[8],  (const float*)d_in[14]};
    const float* ASRC[3] = {(const float*)d_in[3],  (const float*)d_in[9],  (const float*)d_in[15]};
    const float* ADST[3] = {(const float*)d_in[4],  (const float*)d_in[10], (const float*)d_in[16]};
    const float* BB[3]   = {(const float*)d_in[5],  (const float*)d_in[11], (const float*)d_in[17]};
    const float* SW[3]   = {(const float*)d_in[6],  (const float*)d_in[12], (const float*)d_in[18]};
    const float* SB[3]   = {(const float*)d_in[7],  (const float*)d_in[13], (const float*)d_in[19]};
    const int FIN[3] = {128, HC, HC};

    float *ps, *pd;
    int *pdeg, *pcur, *prp, *pcsr, *pbsum;
    __half *pbh, *pa16, *ph16, *pacc;
    cudaGetSymbolAddress((void**)&ph16, g_h16);
    cudaGetSymbolAddress((void**)&pacc, g_acc);
    cudaGetSymbolAddress((void**)&ps,   g_s);
    cudaGetSymbolAddress((void**)&pd,   g_d);
    cudaGetSymbolAddress((void**)&pdeg, g_deg);
    cudaGetSymbolAddress((void**)&pcur, g_cur);
    cudaGetSymbolAddress((void**)&prp,  g_rp);
    cudaGetSymbolAddress((void**)&pcsr, g_csr);
    cudaGetSymbolAddress((void**)&pbsum,g_bsum);
    cudaGetSymbolAddress((void**)&pbh,  g_bh);
    cudaGetSymbolAddress((void**)&pa16, g_a16);

    cudaFuncSetAttribute(gemm_mma_kernel,
                         cudaFuncAttributeMaxDynamicSharedMemorySize, GEMM_SMEM);

    const dim3 gemmGrid(4, (nN + 127) / 128);
    const int eBlocks   = (nTot + 255) / 256;
    const int sdBlocks  = (nN * 32 + 255) / 256;
    const int aggBlocks = (nN * 32 + 255) / 256;
    const int scanBlocks = (nN + SCAN_BLK - 1) / SCAN_BLK;

    prep_kernel<<<1280, 256>>>(W[0], SW[0], W[1], SW[1], W[2], SW[2],
                               pbh, pdeg);
    conv_a_kernel<<<(nN * 128 + 255) / 256, 256>>>(x0, pa16, nN * 128);
    hist_kernel<<<eBlocks, 256>>>(ei, pdeg, nE, nTot);

    // layer-1 GEMM (profiled by ncu)
    gemm_mma_kernel<<<gemmGrid, 256, GEMM_SMEM>>>(pa16, pbh, ph16, pacc,
                                                  BB[0], SB[0], nN, 128);

    scan1_kernel<<<scanBlocks, 256>>>(pdeg, pbsum, nN);
    scan2_kernel<<<1, 256>>>(pbsum, scanBlocks);
    scan3_kernel<<<scanBlocks, 256>>>(pdeg, pbsum, prp, pcur, nN);
    scatter_kernel<<<eBlocks, 256>>>(ei, pcur, pcsr, nE, nTot);

    for (int l = 0; l < 3; l++) {
        if (l > 0) {
            __half* bh = pbh + (size_t)l * 131072;
            gemm_mma_kernel<<<gemmGrid, 256, GEMM_SMEM>>>(pa16, bh, ph16, pacc,
                                                          BB[l], SB[l], nN, FIN[l]);
        }
        compute_sd_kernel<<<sdBlocks, 256>>>(ph16, ASRC[l], ADST[l], ps, pd, nN);
        float* xout = (l == 2) ? (float*)d_out : nullptr;
        __half* x16 = (l == 2) ? nullptr : pa16;
        node_agg_kernel<<<aggBlocks, 256>>>(prp, pcsr, ps, pd, ph16, pacc,
                                            xout, x16, nN);
    }
}

// round 17
// speedup vs baseline: 1.2488x; 1.0211x over previous
#include <cuda_runtime.h>
#include <cuda_fp16.h>
#include <cstdint>

// ---------------------------------------------------------------------------
// GATEncoder: 3 layers of (GATConv + linear skip + ELU)
// N=50000, E=800000 (+N self loops), IN=128, H=4, C=64, HC=256
// Round 17: CSR build forked onto a 2nd stream (hidden under layer-1 GEMM);
//           4-stage cp.async GEMM pipeline (3 chunks in flight).
// ---------------------------------------------------------------------------

#define NNODES 50000
#define NEDGES 800000
#define ETOT   (NEDGES + NNODES)
#define HC     256
#define SCAN_BLK 512
#define SSTR 40
#define STG  (128 * SSTR)              // halves per matrix per stage
#define STAGE_B (2 * STG * 2)          // bytes per stage: A, B
#define GEMM_SMEM (4 * STAGE_B)        // 4 stages = 81920 B

// ------------------------- static device scratch ---------------------------
__device__ __half g_h16[(size_t)NNODES * HC];
__device__ __half g_acc[(size_t)NNODES * HC];
__device__ float g_s   [(size_t)NNODES * 4];
__device__ float g_d   [(size_t)NNODES * 4];
__device__ int   g_deg [NNODES];
__device__ int   g_cur [NNODES];
__device__ int   g_rp  [NNODES + 1];
__device__ int   g_csr [ETOT];
__device__ int   g_bsum[256];
__device__ __half g_a16[(size_t)NNODES * HC];
__device__ __half g_bh [3][131072];

// ------------------------- helpers ----------------------------------------
__device__ __forceinline__ float lrelu(float v) { return v > 0.f ? v : 0.2f * v; }

__device__ __forceinline__ void mma16816(float* d, const uint32_t* a,
                                         uint32_t b0, uint32_t b1) {
    asm volatile(
        "mma.sync.aligned.m16n8k16.row.col.f32.f16.f16.f32 "
        "{%0,%1,%2,%3}, {%4,%5,%6,%7}, {%8,%9}, {%0,%1,%2,%3};"
        : "+f"(d[0]), "+f"(d[1]), "+f"(d[2]), "+f"(d[3])
        : "r"(a[0]), "r"(a[1]), "r"(a[2]), "r"(a[3]), "r"(b0), "r"(b1));
}

__device__ __forceinline__ void cp16(uint32_t dst, const __half* src, int srcsz) {
    asm volatile("cp.async.cg.shared.global [%0], [%1], 16, %2;"
                 :: "r"(dst), "l"(src), "r"(srcsz));
}

__device__ __forceinline__ void ldm_x4(uint32_t* r, uint32_t addr) {
    asm volatile("ldmatrix.sync.aligned.m8n8.x4.shared.b16 {%0,%1,%2,%3}, [%4];"
                 : "=r"(r[0]), "=r"(r[1]), "=r"(r[2]), "=r"(r[3]) : "r"(addr));
}
__device__ __forceinline__ void ldm_x2(uint32_t& r0, uint32_t& r1, uint32_t addr) {
    asm volatile("ldmatrix.sync.aligned.m8n8.x2.shared.b16 {%0,%1}, [%2];"
                 : "=r"(r0), "=r"(r1) : "r"(addr));
}

// ------------------------- prep (weights only) ------------------------------
__global__ void prep_kernel(const float* __restrict__ W1, const float* __restrict__ SW1,
                            const float* __restrict__ W2, const float* __restrict__ SW2,
                            const float* __restrict__ W3, const float* __restrict__ SW3,
                            __half* __restrict__ bh) {
    const int idx = blockIdx.x * blockDim.x + threadIdx.x;
    if (idx >= 327680) return;
    int l, which, mi, K;
    const float* src;
    if (idx < 65536)       { l = 0; K = 128; const int r = idx;          which = r >> 15; mi = r & 32767; src = which ? SW1 : W1; }
    else if (idx < 196608) { l = 1; K = 256; const int r = idx - 65536;  which = r >> 16; mi = r & 65535; src = which ? SW2 : W2; }
    else                   { l = 2; K = 256; const int r = idx - 196608; which = r >> 16; mi = r & 65535; src = which ? SW3 : W3; }
    const int k = mi >> 8;
    const int n = mi & 255;
    const size_t off = (size_t)l * 131072 + (size_t)(which * 256 + n) * K + k;
    bh[off] = __float2half_rn(src[mi]);
}

// ------------------------- conv_a -------------------------------------------
__global__ void conv_a_kernel(const float* __restrict__ X,
                              __half* __restrict__ a16, int total) {
    const int idx = blockIdx.x * blockDim.x + threadIdx.x;
    if (idx >= total) return;
    a16[idx] = __float2half_rn(X[idx]);
}

// ------------------------- fused dual GEMM: fp16, 4-stage, ldmatrix --------
__global__ __launch_bounds__(256, 2)
void gemm_mma_kernel(const __half* __restrict__ A,
                     const __half* __restrict__ Bh,
                     __half* __restrict__ Ch16,
                     __half* __restrict__ Cacc16,
                     const float* __restrict__ bias1,
                     const float* __restrict__ bias2,
                     int M, int K) {
    extern __shared__ __half smem[];

    const int tid = threadIdx.x;
    const int wid = tid >> 5;
    const int lane = tid & 31;
    const int qr = lane >> 2;
    const int qc = (lane & 3) * 2;
    const int warp_m = (wid >> 2) * 64;
    const int warp_n = (wid & 3) * 32;
    const int m0 = blockIdx.y * 128;
    const int n0 = blockIdx.x * 128;

    float d[4][4][4];
#pragma unroll
    for (int mt = 0; mt < 4; mt++)
#pragma unroll
        for (int nt = 0; nt < 4; nt++)
#pragma unroll
            for (int r = 0; r < 4; r++) d[mt][nt][r] = 0.f;

    const int ar = tid >> 1;
    const int akh = (tid & 1) * 16;
    const int aguard = (m0 + ar < M) ? 16 : 0;
    const size_t abase = (size_t)(m0 + ar) * K + akh;
    const size_t bbase = (size_t)(n0 + ar) * K + akh;

    const uint32_t sbase = (uint32_t)__cvta_generic_to_shared(smem);
    const uint32_t stOfs = (uint32_t)(ar * SSTR + akh) * 2;

    uint32_t aofs[4], bofs[4];
#pragma unroll
    for (int mt = 0; mt < 4; mt++)
        aofs[mt] = (uint32_t)((warp_m + mt * 16 + (lane & 15)) * SSTR +
                              ((lane >> 4) << 3)) * 2;
#pragma unroll
    for (int nt = 0; nt < 4; nt++)
        bofs[nt] = (uint32_t)((warp_n + nt * 8 + (lane & 7)) * SSTR +
                              (((lane >> 3) & 1) << 3)) * 2;

    const int nch = K >> 5;   // >= 4 always

    // prologue: chunks 0,1,2 into stages 0,1,2
#pragma unroll
    for (int p = 0; p < 3; p++) {
        const uint32_t st = sbase + p * STAGE_B;
        const int kp = p << 5;
        cp16(st + stOfs,                A + abase + kp,      aguard);
        cp16(st + stOfs + 16,           A + abase + kp + 8,  aguard);
        cp16(st + STG * 2 + stOfs,      Bh + bbase + kp,     16);
        cp16(st + STG * 2 + stOfs + 16, Bh + bbase + kp + 8, 16);
        asm volatile("cp.async.commit_group;");
    }

    int stage = 0;
    for (int ch = 0; ch < nch; ch++) {
        const int rem = nch - ch - 1;
        if (rem >= 2)      asm volatile("cp.async.wait_group 2;");
        else if (rem == 1) asm volatile("cp.async.wait_group 1;");
        else               asm volatile("cp.async.wait_group 0;");
        __syncthreads();

        if (ch + 3 < nch) {
            const uint32_t st = sbase + ((stage + 3) & 3) * STAGE_B;
            const int kp = (ch + 3) << 5;
            cp16(st + stOfs,                A + abase + kp,      aguard);
            cp16(st + stOfs + 16,           A + abase + kp + 8,  aguard);
            cp16(st + STG * 2 + stOfs,      Bh + bbase + kp,     16);
            cp16(st + STG * 2 + stOfs + 16, Bh + bbase + kp + 8, 16);
            asm volatile("cp.async.commit_group;");
        }

        const uint32_t stA  = sbase + stage * STAGE_B;
        const uint32_t stBh = stA + STG * 2;

#pragma unroll
        for (int ks = 0; ks < 2; ks++) {
            const uint32_t kb = ks * 32;
            uint32_t ah[4][4];
#pragma unroll
            for (int mt = 0; mt < 4; mt++)
                ldm_x4(ah[mt], stA + aofs[mt] + kb);
#pragma unroll
            for (int nt = 0; nt < 4; nt++) {
                uint32_t bh0, bh1;
                ldm_x2(bh0, bh1, stBh + bofs[nt] + kb);
#pragma unroll
                for (int mt = 0; mt < 4; mt++)
                    mma16816(d[mt][nt], ah[mt], bh0, bh1);
            }
        }
        stage = (stage + 1) & 3;
    }

#pragma unroll
    for (int nt = 0; nt < 4; nt++) {
        const int gcol = n0 + warp_n + nt * 8 + qc;
        if (gcol < 256) {
#pragma unroll
            for (int mt = 0; mt < 4; mt++) {
                const int r0 = m0 + warp_m + mt * 16 + qr;
                if (r0 < M) {
                    __half2 v = __floats2half2_rn(d[mt][nt][0], d[mt][nt][1]);
                    *(__half2*)&Ch16[(size_t)r0 * HC + gcol] = v;
                }
                if (r0 + 8 < M) {
                    __half2 v = __floats2half2_rn(d[mt][nt][2], d[mt][nt][3]);
                    *(__half2*)&Ch16[(size_t)(r0 + 8) * HC + gcol] = v;
                }
            }
        } else {
            const int col = gcol - 256;
            const float bv0 = bias1[col] + bias2[col];
            const float bv1 = bias1[col + 1] + bias2[col + 1];
#pragma unroll
            for (int mt = 0; mt < 4; mt++) {
                const int r0 = m0 + warp_m + mt * 16 + qr;
                if (r0 < M) {
                    __half2 v = __floats2half2_rn(d[mt][nt][0] + bv0, d[mt][nt][1] + bv1);
                    *(__half2*)&Cacc16[(size_t)r0 * HC + col] = v;
                }
                if (r0 + 8 < M) {
                    __half2 v = __floats2half2_rn(d[mt][nt][2] + bv0, d[mt][nt][3] + bv1);
                    *(__half2*)&Cacc16[(size_t)(r0 + 8) * HC + col] = v;
                }
            }
        }
    }
}

// ------------------------- CSR build ---------------------------------------
__global__ void hist_kernel(const int* __restrict__ ei, int* __restrict__ deg,
                            int nE, int nTot) {
    const int e = blockIdx.x * blockDim.x + threadIdx.x;
    if (e >= nTot) return;
    const int d = (e < nE) ? ei[nE + e] : (e - nE);
    atomicAdd(&deg[d], 1);
}

__global__ void scan1_kernel(const int* __restrict__ deg, int* __restrict__ bsum,
                             int n) {
    __shared__ int sh[256];
    const int b0 = blockIdx.x * SCAN_BLK;
    const int t = threadIdx.x;
    int s = 0;
    if (b0 + t < n)       s += deg[b0 + t];
    if (b0 + 256 + t < n) s += deg[b0 + 256 + t];
    sh[t] = s;
    __syncthreads();
    for (int off = 128; off > 0; off >>= 1) {
        if (t < off) sh[t] += sh[t + off];
        __syncthreads();
    }
    if (t == 0) bsum[blockIdx.x] = sh[0];
}

__global__ void scan2_kernel(int* __restrict__ bsum, int nb) {
    __shared__ int sh[256];
    const int t = threadIdx.x;
    sh[t] = (t < nb) ? bsum[t] : 0;
    __syncthreads();
    for (int off = 1; off < 256; off <<= 1) {
        const int v = (t >= off) ? sh[t - off] : 0;
        __syncthreads();
        sh[t] += v;
        __syncthreads();
    }
    if (t < nb) bsum[t] = (t == 0) ? 0 : sh[t - 1];
}

__global__ void scan3_kernel(const int* __restrict__ deg,
                             const int* __restrict__ bsum,
                             int* __restrict__ rp, int* __restrict__ cur,
                             int n) {
    __shared__ int sh[SCAN_BLK];
    const int b0 = blockIdx.x * SCAN_BLK;
    const int t = threadIdx.x;
    const int v0 = (b0 + t < n) ? deg[b0 + t] : 0;
    const int v1 = (b0 + 256 + t < n) ? deg[b0 + 256 + t] : 0;
    sh[t] = v0;
    sh[256 + t] = v1;
    __syncthreads();
    for (int off = 1; off < SCAN_BLK; off <<= 1) {
        const int a0 = (t >= off) ? sh[t - off] : 0;
        const int a1 = (t + 256 >= off) ? sh[t + 256 - off] : 0;
        __syncthreads();
        sh[t] += a0;
        sh[256 + t] += a1;
        __syncthreads();
    }
    const int base = bsum[blockIdx.x];
    if (b0 + t < n) {
        const int ex = base + sh[t] - v0;
        rp[b0 + t] = ex;
        cur[b0 + t] = ex;
    }
    if (b0 + 256 + t < n) {
        const int ex = base + sh[256 + t] - v1;
        rp[b0 + 256 + t] = ex;
        cur[b0 + 256 + t] = ex;
    }
    if (blockIdx.x == gridDim.x - 1 && t == 0) rp[n] = base + sh[SCAN_BLK - 1];
}

__global__ void scatter_kernel(const int* __restrict__ ei, int* __restrict__ cur,
                               int* __restrict__ csr, int nE, int nTot) {
    const int e = blockIdx.x * blockDim.x + threadIdx.x;
    if (e >= nTot) return;
    int s, d;
    if (e < nE) { s = ei[e]; d = ei[nE + e]; }
    else        { s = d = e - nE; }
    const int pos = atomicAdd(&cur[d], 1);
    csr[pos] = s;
}

// ------------------------- s/d per node (fp16 h) ----------------------------
__global__ void compute_sd_kernel(const __half* __restrict__ gh,
                                  const float* __restrict__ a_src,
                                  const float* __restrict__ a_dst,
                                  float* __restrict__ gs, float* __restrict__ gd,
                                  int n_nodes) {
    const int warp = (blockIdx.x * blockDim.x + threadIdx.x) >> 5;
    const int lane = threadIdx.x & 31;
    if (warp >= n_nodes) return;
    const __half* hr = gh + (size_t)warp * HC;
#pragma unroll
    for (int h = 0; h < 4; h++) {
        const float h1 = __half2float(hr[h * 64 + lane]);
        const float h2 = __half2float(hr[h * 64 + 32 + lane]);
        float s = h1 * a_src[h * 64 + lane] + h2 * a_src[h * 64 + 32 + lane];
        float d = h1 * a_dst[h * 64 + lane] + h2 * a_dst[h * 64 + 32 + lane];
#pragma unroll
        for (int off = 16; off > 0; off >>= 1) {
            s += __shfl_down_sync(0xFFFFFFFFu, s, off);
            d += __shfl_down_sync(0xFFFFFFFFu, d, off);
        }
        if (lane == 0) {
            gs[warp * 4 + h] = s;
            gd[warp * 4 + h] = d;
        }
    }
}

// ------------------------- fused softmax + aggregate + skip + ELU ----------
__global__ __launch_bounds__(256)
void node_agg_kernel(const int* __restrict__ rp, const int* __restrict__ csr,
                     const float* __restrict__ gs, const float* __restrict__ gd,
                     const __half* __restrict__ gh, const __half* __restrict__ gskip,
                     float* __restrict__ xout,
                     __half* __restrict__ x16,
                     int nN) {
    const int v = (blockIdx.x * blockDim.x + threadIdx.x) >> 5;
    const int lane = threadIdx.x & 31;
    if (v >= nN) return;

    const int b = rp[v];
    const int e = rp[v + 1];
    const float4 dv = ((const float4*)gd)[v];

    float m0 = -1e30f, m1 = -1e30f, m2 = -1e30f, m3 = -1e30f;
    for (int i = b + lane; i < e; i += 32) {
        const float4 sv = ((const float4*)gs)[csr[i]];
        m0 = fmaxf(m0, lrelu(sv.x + dv.x));
        m1 = fmaxf(m1, lrelu(sv.y + dv.y));
        m2 = fmaxf(m2, lrelu(sv.z + dv.z));
        m3 = fmaxf(m3, lrelu(sv.w + dv.w));
    }
#pragma unroll
    for (int off = 16; off > 0; off >>= 1) {
        m0 = fmaxf(m0, __shfl_xor_sync(0xFFFFFFFFu, m0, off));
        m1 = fmaxf(m1, __shfl_xor_sync(0xFFFFFFFFu, m1, off));
        m2 = fmaxf(m2, __shfl_xor_sync(0xFFFFFFFFu, m2, off));
        m3 = fmaxf(m3, __shfl_xor_sync(0xFFFFFFFFu, m3, off));
    }

    float n0 = 0.f, n1 = 0.f, n2 = 0.f, n3 = 0.f;
    for (int i = b + lane; i < e; i += 32) {
        const float4 sv = ((const float4*)gs)[csr[i]];
        n0 += expf(lrelu(sv.x + dv.x) - m0);
        n1 += expf(lrelu(sv.y + dv.y) - m1);
        n2 += expf(lrelu(sv.z + dv.z) - m2);
        n3 += expf(lrelu(sv.w + dv.w) - m3);
    }
#pragma unroll
    for (int off = 16; off > 0; off >>= 1) {
        n0 += __shfl_xor_sync(0xFFFFFFFFu, n0, off);
        n1 += __shfl_xor_sync(0xFFFFFFFFu, n1, off);
        n2 += __shfl_xor_sync(0xFFFFFFFFu, n2, off);
        n3 += __shfl_xor_sync(0xFFFFFFFFu, n3, off);
    }

    const int h = lane >> 3;
    const float dvh  = (h < 2) ? (h == 0 ? dv.x : dv.y) : (h == 2 ? dv.z : dv.w);
    const float mh   = (h < 2) ? (h == 0 ? m0 : m1) : (h == 2 ? m2 : m3);
    const float dnh  = (h < 2) ? (h == 0 ? n0 : n1) : (h == 2 ? n2 : n3);
    const float invh = 1.f / (dnh + 1e-16f);

    float4 a0 = make_float4(0.f, 0.f, 0.f, 0.f);
    float4 a1 = make_float4(0.f, 0.f, 0.f, 0.f);
#pragma unroll 2
    for (int i = b; i < e; i++) {
        const int s = csr[i];
        const float sval = gs[s * 4 + h];
        const float al = expf(lrelu(sval + dvh) - mh) * invh;
        const uint4 hv = *(const uint4*)(gh + (size_t)s * HC + lane * 8);
        const float2 f0 = __half22float2(*(const __half2*)&hv.x);
        const float2 f1 = __half22float2(*(const __half2*)&hv.y);
        const float2 f2 = __half22float2(*(const __half2*)&hv.z);
        const float2 f3 = __half22float2(*(const __half2*)&hv.w);
        a0.x = fmaf(f0.x, al, a0.x);  a0.y = fmaf(f0.y, al, a0.y);
        a0.z = fmaf(f1.x, al, a0.z);  a0.w = fmaf(f1.y, al, a0.w);
        a1.x = fmaf(f2.x, al, a1.x);  a1.y = fmaf(f2.y, al, a1.y);
        a1.z = fmaf(f3.x, al, a1.z);  a1.w = fmaf(f3.y, al, a1.w);
    }

    const uint4 sv4 = *(const uint4*)(gskip + (size_t)v * HC + lane * 8);
    const float2 s0 = __half22float2(*(const __half2*)&sv4.x);
    const float2 s1 = __half22float2(*(const __half2*)&sv4.y);
    const float2 s2 = __half22float2(*(const __half2*)&sv4.z);
    const float2 s3 = __half22float2(*(const __half2*)&sv4.w);
    float4 o0, o1;
    o0.x = a0.x + s0.x;  o0.y = a0.y + s0.y;  o0.z = a0.z + s1.x;  o0.w = a0.w + s1.y;
    o1.x = a1.x + s2.x;  o1.y = a1.y + s2.y;  o1.z = a1.z + s3.x;  o1.w = a1.w + s3.y;
    o0.x = o0.x > 0.f ? o0.x : expm1f(o0.x);
    o0.y = o0.y > 0.f ? o0.y : expm1f(o0.y);
    o0.z = o0.z > 0.f ? o0.z : expm1f(o0.z);
    o0.w = o0.w > 0.f ? o0.w : expm1f(o0.w);
    o1.x = o1.x > 0.f ? o1.x : expm1f(o1.x);
    o1.y = o1.y > 0.f ? o1.y : expm1f(o1.y);
    o1.z = o1.z > 0.f ? o1.z : expm1f(o1.z);
    o1.w = o1.w > 0.f ? o1.w : expm1f(o1.w);

    if (xout) {
        float4* op = (float4*)(xout + (size_t)v * HC) + lane * 2;
        op[0] = o0;
        op[1] = o1;
    }
    if (x16) {
        __half2 p0 = __floats2half2_rn(o0.x, o0.y);
        __half2 p1 = __floats2half2_rn(o0.z, o0.w);
        __half2 p2 = __floats2half2_rn(o1.x, o1.y);
        __half2 p3 = __floats2half2_rn(o1.z, o1.w);
        uint4 u = make_uint4(*(uint32_t*)&p0, *(uint32_t*)&p1,
                             *(uint32_t*)&p2, *(uint32_t*)&p3);
        *(uint4*)(x16 + (size_t)v * HC + lane * 8) = u;
    }
}

// ---------------------------------------------------------------------------
extern "C" void kernel_launch(void* const* d_in, const int* in_sizes, int n_in,
                              void* d_out, int out_size) {
    const float* x0 = (const float*)d_in[0];
    const int* ei = (const int*)d_in[1];
    const int nE = in_sizes[1] / 2;
    const int nN = NNODES;
    const int nTot = nE + nN;

    const float* W[3]    = {(const float*)d_in[2],  (const float*)d_in[8],  (const float*)d_in[14]};
    const float* ASRC[3] = {(const float*)d_in[3],  (const float*)d_in[9],  (const float*)d_in[15]};
    const float* ADST[3] = {(const float*)d_in[4],  (const float*)d_in[10], (const float*)d_in[16]};
    const float* BB[3]   = {(const float*)d_in[5],  (const float*)d_in[11], (const float*)d_in[17]};
    const float* SW[3]   = {(const float*)d_in[6],  (const float*)d_in[12], (const float*)d_in[18]};
    const float* SB[3]   = {(const float*)d_in[7],  (const float*)d_in[13], (const float*)d_in[19]};
    const int FIN[3] = {128, HC, HC};

    float *ps, *pd;
    int *pdeg, *pcur, *prp, *pcsr, *pbsum;
    __half *pbh, *pa16, *ph16, *pacc;
    cudaGetSymbolAddress((void**)&ph16, g_h16);
    cudaGetSymbolAddress((void**)&pacc, g_acc);
    cudaGetSymbolAddress((void**)&ps,   g_s);
    cudaGetSymbolAddress((void**)&pd,   g_d);
    cudaGetSymbolAddress((void**)&pdeg, g_deg);
    cudaGetSymbolAddress((void**)&pcur, g_cur);
    cudaGetSymbolAddress((void**)&prp,  g_rp);
    cudaGetSymbolAddress((void**)&pcsr, g_csr);
    cudaGetSymbolAddress((void**)&pbsum,g_bsum);
    cudaGetSymbolAddress((void**)&pbh,  g_bh);
    cudaGetSymbolAddress((void**)&pa16, g_a16);

    cudaFuncSetAttribute(gemm_mma_kernel,
                         cudaFuncAttributeMaxDynamicSharedMemorySize, GEMM_SMEM);

    const dim3 gemmGrid(4, (nN + 127) / 128);
    const int eBlocks   = (nTot + 255) / 256;
    const int sdBlocks  = (nN * 32 + 255) / 256;
    const int aggBlocks = (nN * 32 + 255) / 256;
    const int scanBlocks = (nN + SCAN_BLK - 1) / SCAN_BLK;

    // ---- fork a second stream for the CSR build ----
    cudaStream_t s2;
    cudaStreamCreateWithFlags(&s2, cudaStreamNonBlocking);
    cudaEvent_t evFork, evJoin;
    cudaEventCreateWithFlags(&evFork, cudaEventDisableTiming);
    cudaEventCreateWithFlags(&evJoin, cudaEventDisableTiming);

    cudaEventRecord(evFork, 0);
    cudaStreamWaitEvent(s2, evFork, 0);

    // stream s2: CSR build (independent of weights/features)
    cudaMemsetAsync(pdeg, 0, NNODES * sizeof(int), s2);
    hist_kernel<<<eBlocks, 256, 0, s2>>>(ei, pdeg, nE, nTot);
    scan1_kernel<<<scanBlocks, 256, 0, s2>>>(pdeg, pbsum, nN);
    scan2_kernel<<<1, 256, 0, s2>>>(pbsum, scanBlocks);
    scan3_kernel<<<scanBlocks, 256, 0, s2>>>(pdeg, pbsum, prp, pcur, nN);
    scatter_kernel<<<eBlocks, 256, 0, s2>>>(ei, pcur, pcsr, nE, nTot);
    cudaEventRecord(evJoin, s2);

    // stream 0: weights/features/GEMM path
    prep_kernel<<<1280, 256>>>(W[0], SW[0], W[1], SW[1], W[2], SW[2], pbh);
    conv_a_kernel<<<(nN * 128 + 255) / 256, 256>>>(x0, pa16, nN * 128);
    gemm_mma_kernel<<<gemmGrid, 256, GEMM_SMEM>>>(pa16, pbh, ph16, pacc,
                                                  BB[0], SB[0], nN, 128);
    compute_sd_kernel<<<sdBlocks, 256>>>(ph16, ASRC[0], ADST[0], ps, pd, nN);

    // join: node_agg needs the CSR
    cudaStreamWaitEvent(0, evJoin, 0);

    for (int l = 0; l < 3; l++) {
        if (l > 0) {
            __half* bh = pbh + (size_t)l * 131072;
            gemm_mma_kernel<<<gemmGrid, 256, GEMM_SMEM>>>(pa16, bh, ph16, pacc,
                                                          BB[l], SB[l], nN, FIN[l]);
            compute_sd_kernel<<<sdBlocks, 256>>>(ph16, ASRC[l], ADST[l], ps, pd, nN);
        }
        float* xout = (l == 2) ? (float*)d_out : nullptr;
        __half* x16 = (l == 2) ? nullptr : pa16;
        node_agg_kernel<<<aggBlocks, 256>>>(prp, pcsr, ps, pd, ph16, pacc,
                                            xout, x16, nN);
    }
}